// round 1
// baseline (speedup 1.0000x reference)
#include <cuda_runtime.h>
#include <math.h>

#define NB 2
#define CXC 64
#define CYC 128
#define CO  64
#define DD  16
#define HH  64
#define WW  64
#define DYI 8
#define HYI 32
#define WYI 32
#define PX  (DD*HH*WW)    /* 65536 */
#define PY  (DYI*HYI*WYI) /* 8192  */

// ---------------- scratch (device globals; no allocation) ----------------
__device__ float g_xmean[NB*CXC];
__device__ float g_wcombT[NB*CXC*CO];            // [n][i][o]
__device__ float g_hf[NB*CO*PY];                 // 4 MB
__device__ float g_concat[(size_t)NB*128*PX];    // 64 MB: ch 0-63 hf_up, 64-127 low
__device__ float g_flow[NB*3*PX];                // 4.7 MB

// ---------------- K1: xmean[n][c] = mean over spatial of x ----------------
__global__ void k_xmean(const float* __restrict__ x) {
    int nc = blockIdx.x;                     // 0..127
    const float4* p = (const float4*)(x + (size_t)nc * PX);
    float s = 0.f;
    for (int i = threadIdx.x; i < PX/4; i += 256) {
        float4 v = p[i];
        s += (v.x + v.y) + (v.z + v.w);
    }
    #pragma unroll
    for (int o = 16; o > 0; o >>= 1) s += __shfl_xor_sync(0xffffffffu, s, o);
    __shared__ float sm[8];
    if ((threadIdx.x & 31) == 0) sm[threadIdx.x >> 5] = s;
    __syncthreads();
    if (threadIdx.x < 8) {
        float t = sm[threadIdx.x];
        #pragma unroll
        for (int o = 4; o > 0; o >>= 1) t += __shfl_xor_sync(0xffu, t, o, 8);
        if (threadIdx.x == 0) g_xmean[nc] = t * (1.f / PX);
    }
}

// ---- K2: fold SE attention into one 64x64 matrix per batch (transposed) ----
__global__ void k_prep(const float* __restrict__ wdl,
                       const float* __restrict__ wa,
                       const float* __restrict__ wc) {
    int n = blockIdx.x, t = threadIdx.x;     // 64 threads
    __shared__ float xm[64], pooled[64], scale[64];
    xm[t] = g_xmean[n*64 + t];
    __syncthreads();
    float s = 0.f;
    for (int i = 0; i < 64; i++) s += wdl[t*64 + i] * xm[i];
    pooled[t] = s;
    __syncthreads();
    float a = 0.f;
    for (int i = 0; i < 64; i++) a += wa[t*64 + i] * pooled[i];
    scale[t] = 1.f + 1.f / (1.f + expf(-a));
    __syncthreads();
    // wcombT[n][i][t] = sum_c wc[t,c]*scale[c]*wdl[c,i]
    for (int i = 0; i < 64; i++) {
        float acc = 0.f;
        for (int c = 0; c < 64; c++) acc += wc[t*64 + c] * scale[c] * wdl[c*64 + i];
        g_wcombT[(n*64 + i)*64 + t] = acc;
    }
}

// ---------------- K3: hf_small = w_down_h @ y  (128 -> 64) ----------------
__global__ void k_hf(const float* __restrict__ y, const float* __restrict__ wdh) {
    __shared__ float wT[128][64];            // wT[i][o]
    int tid = threadIdx.x;                   // 128
    for (int idx = tid; idx < 128*64; idx += 128) {
        int o = idx >> 7, i = idx & 127;
        wT[i][o] = wdh[idx];
    }
    __syncthreads();
    int n = blockIdx.y;
    int p = blockIdx.x*128 + tid;
    const float* yp = y + (size_t)n*CYC*PY + p;
    float acc[64];
    #pragma unroll
    for (int o = 0; o < 64; o++) acc[o] = 0.f;
    for (int i = 0; i < 128; i++) {
        float v = yp[(size_t)i*PY];
        #pragma unroll
        for (int o4 = 0; o4 < 16; o4++) {
            float4 w4 = *(const float4*)&wT[i][o4*4];
            acc[o4*4+0] = fmaf(w4.x, v, acc[o4*4+0]);
            acc[o4*4+1] = fmaf(w4.y, v, acc[o4*4+1]);
            acc[o4*4+2] = fmaf(w4.z, v, acc[o4*4+2]);
            acc[o4*4+3] = fmaf(w4.w, v, acc[o4*4+3]);
        }
    }
    float* op = g_hf + (size_t)n*CO*PY + p;
    #pragma unroll
    for (int o = 0; o < 64; o++) op[(size_t)o*PY] = acc[o];
}

// -------- K4: low = M_n @ x per voxel -> concat channels 64..127 ----------
__global__ void k_low(const float* __restrict__ x) {
    __shared__ float wT[64][64];             // wT[i][o]
    int tid = threadIdx.x;                   // 128
    int n = blockIdx.y;
    for (int idx = tid; idx < 64*64; idx += 128)
        ((float*)wT)[idx] = g_wcombT[n*4096 + idx];
    __syncthreads();
    int p = blockIdx.x*128 + tid;
    const float* xp = x + (size_t)n*CXC*PX + p;
    float acc[64];
    #pragma unroll
    for (int o = 0; o < 64; o++) acc[o] = 0.f;
    for (int i = 0; i < 64; i++) {
        float v = xp[(size_t)i*PX];
        #pragma unroll
        for (int o4 = 0; o4 < 16; o4++) {
            float4 w4 = *(const float4*)&wT[i][o4*4];
            acc[o4*4+0] = fmaf(w4.x, v, acc[o4*4+0]);
            acc[o4*4+1] = fmaf(w4.y, v, acc[o4*4+1]);
            acc[o4*4+2] = fmaf(w4.z, v, acc[o4*4+2]);
            acc[o4*4+3] = fmaf(w4.w, v, acc[o4*4+3]);
        }
    }
    float* op = g_concat + (size_t)(n*128 + 64)*PX + p;
    #pragma unroll
    for (int o = 0; o < 64; o++) op[(size_t)o*PX] = acc[o];
}

// ------ K5: trilinear upsample (align_corners) -> concat channels 0..63 ----
__global__ void k_up() {
    int idx = blockIdx.x*256 + threadIdx.x;  // over NB*CO*PX
    int w = idx & 63;
    int h = (idx >> 6) & 63;
    int d = (idx >> 12) & 15;
    int c = (idx >> 16) & 63;
    int n = idx >> 22;
    float pw = w * (31.f/63.f);
    float ph = h * (31.f/63.f);
    float pd = d * (7.f/15.f);
    int w0 = (int)pw; if (w0 > 31) w0 = 31;
    int h0 = (int)ph; if (h0 > 31) h0 = 31;
    int d0 = (int)pd; if (d0 > 7)  d0 = 7;
    float fw = pw - w0, fh = ph - h0, fd = pd - d0;
    int w1 = min(w0 + 1, 31), h1 = min(h0 + 1, 31), d1 = min(d0 + 1, 7);
    const float* hp = g_hf + (size_t)(n*CO + c)*PY;
    float v000 = __ldg(hp + (d0*32 + h0)*32 + w0);
    float v001 = __ldg(hp + (d0*32 + h0)*32 + w1);
    float v010 = __ldg(hp + (d0*32 + h1)*32 + w0);
    float v011 = __ldg(hp + (d0*32 + h1)*32 + w1);
    float v100 = __ldg(hp + (d1*32 + h0)*32 + w0);
    float v101 = __ldg(hp + (d1*32 + h0)*32 + w1);
    float v110 = __ldg(hp + (d1*32 + h1)*32 + w0);
    float v111 = __ldg(hp + (d1*32 + h1)*32 + w1);
    float c00 = v000*(1.f-fw) + v001*fw;
    float c01 = v010*(1.f-fw) + v011*fw;
    float c10 = v100*(1.f-fw) + v101*fw;
    float c11 = v110*(1.f-fw) + v111*fw;
    float c0  = c00*(1.f-fh) + c01*fh;
    float c1  = c10*(1.f-fh) + c11*fh;
    float r   = c0*(1.f-fd) + c1*fd;
    g_concat[(size_t)(n*128 + c)*PX + (idx & 65535)] = r;
}

// ------------- K6: 3x3x3 conv, 128 -> 3, zero padding -> flow -------------
// block (32,8,2): output tile (w=32,h=8,d=2); smem input tile (4 x 10 x 34),
// double buffered; weights staged per-64-channel half, float4-friendly layout.
#define TROW 34
#define TPLANE 340
#define TSIZE 1360
__global__ void k_conv3(const float* __restrict__ wflow) {
    __shared__ float tile[2][TSIZE];
    __shared__ float wsm[64*108];
    int n  = blockIdx.z;
    int d0 = blockIdx.y * 2;
    int h0 = (blockIdx.x >> 1) * 8;
    int w0 = (blockIdx.x & 1) * 32;
    int tx = threadIdx.x, ty = threadIdx.y, tz = threadIdx.z;
    int tid = (tz*8 + ty)*32 + tx;            // 0..511
    const float* inb = g_concat + (size_t)n*128*PX;

    // precompute the 3 load slots this thread fills in the tile
    int e0 = tid, e1 = tid + 512, e2 = tid + 1024;
    int off0 = 0, off1 = 0, off2 = 0;
    bool ok0 = false, ok1 = false, ok2 = false;
    bool live2 = (e2 < TSIZE);
    {
        int e = e0;
        int zz = e / TPLANE; int rr = e - zz*TPLANE; int yy = rr / TROW; int xx = rr - yy*TROW;
        int gz = d0 - 1 + zz, gy = h0 - 1 + yy, gx = w0 - 1 + xx;
        ok0 = ((unsigned)gz < 16u) && ((unsigned)gy < 64u) && ((unsigned)gx < 64u);
        off0 = (gz*64 + gy)*64 + gx;
        e = e1;
        zz = e / TPLANE; rr = e - zz*TPLANE; yy = rr / TROW; xx = rr - yy*TROW;
        gz = d0 - 1 + zz; gy = h0 - 1 + yy; gx = w0 - 1 + xx;
        ok1 = ((unsigned)gz < 16u) && ((unsigned)gy < 64u) && ((unsigned)gx < 64u);
        off1 = (gz*64 + gy)*64 + gx;
        if (live2) {
            e = e2;
            zz = e / TPLANE; rr = e - zz*TPLANE; yy = rr / TROW; xx = rr - yy*TROW;
            gz = d0 - 1 + zz; gy = h0 - 1 + yy; gx = w0 - 1 + xx;
            ok2 = ((unsigned)gz < 16u) && ((unsigned)gy < 64u) && ((unsigned)gx < 64u);
            off2 = (gz*64 + gy)*64 + gx;
        }
    }

    float a0 = 0.f, a1 = 0.f, a2 = 0.f;
    float r0, r1, r2;
    // prefetch ci = 0
    r0 = ok0 ? __ldg(inb + off0) : 0.f;
    r1 = ok1 ? __ldg(inb + off1) : 0.f;
    r2 = (live2 && ok2) ? __ldg(inb + off2) : 0.f;

    for (int half = 0; half < 2; half++) {
        __syncthreads();
        // stage weights for channels [half*64, half*64+64)
        for (int idx = tid; idx < 64*81; idx += 512) {
            int oc = idx % 3; int r = idx / 3; int tap = r % 27; int cil = r / 27;
            int kd = tap / 9, kh = (tap / 3) % 3, kw = tap % 3;
            wsm[cil*108 + (kd*3 + kh)*12 + kw*3 + oc] =
                wflow[oc*(128*27) + (half*64 + cil)*27 + tap];
        }
        __syncthreads();
        for (int cil = 0; cil < 64; cil++) {
            float* tb = tile[cil & 1];
            tb[e0] = r0; tb[e1] = r1;
            if (live2) tb[e2] = r2;
            __syncthreads();
            int cinext = half*64 + cil + 1;
            if (cinext < 128) {
                const float* cb = inb + (size_t)cinext*PX;
                r0 = ok0 ? __ldg(cb + off0) : 0.f;
                r1 = ok1 ? __ldg(cb + off1) : 0.f;
                r2 = (live2 && ok2) ? __ldg(cb + off2) : 0.f;
            }
            const float* wp = wsm + cil*108;
            const float* tbase = tb + tz*TPLANE + ty*TROW + tx;
            #pragma unroll
            for (int kd = 0; kd < 3; kd++) {
                #pragma unroll
                for (int kh = 0; kh < 3; kh++) {
                    const float* row = tbase + kd*TPLANE + kh*TROW;
                    const float4 q0 = *(const float4*)(wp + (kd*3 + kh)*12);
                    const float4 q1 = *(const float4*)(wp + (kd*3 + kh)*12 + 4);
                    const float  q8 = wp[(kd*3 + kh)*12 + 8];
                    float v0 = row[0], v1 = row[1], v2 = row[2];
                    a0 = fmaf(q0.x, v0, a0); a1 = fmaf(q0.y, v0, a1); a2 = fmaf(q0.z, v0, a2);
                    a0 = fmaf(q0.w, v1, a0); a1 = fmaf(q1.x, v1, a1); a2 = fmaf(q1.y, v1, a2);
                    a0 = fmaf(q1.z, v2, a0); a1 = fmaf(q1.w, v2, a1); a2 = fmaf(q8,   v2, a2);
                }
            }
            __syncthreads();
        }
    }
    size_t po = ((size_t)(d0 + tz)*64 + (h0 + ty))*64 + (w0 + tx);
    g_flow[((size_t)n*3 + 0)*PX + po] = a0;
    g_flow[((size_t)n*3 + 1)*PX + po] = a1;
    g_flow[((size_t)n*3 + 2)*PX + po] = a2;
}

// -------- K7: flow warp + trilinear grid sample (zeros padding) ------------
__global__ void k_sample(const float* __restrict__ y, float* __restrict__ out) {
    int p = blockIdx.x*128 + threadIdx.x;     // 0..65535
    int n = blockIdx.y;
    int w = p & 63, h = (p >> 6) & 63, d = p >> 12;
    const float* fp = g_flow + (size_t)n*3*PX + p;
    float f0 = fp[0], f1 = fp[PX], f2 = fp[2*PX];
    float gx = (w + f0) * (1.f/64.f);
    float gy = (h + f1) * (1.f/64.f);
    float gz = (d + f2) * (1.f/16.f);
    float ix = ((gx + 1.f)*32.f - 1.f)*0.5f;
    float iy = ((gy + 1.f)*32.f - 1.f)*0.5f;
    float iz = ((gz + 1.f)*8.f  - 1.f)*0.5f;
    float fx0 = floorf(ix), fy0 = floorf(iy), fz0 = floorf(iz);
    int x0 = (int)fx0, y0 = (int)fy0, z0 = (int)fz0;
    float fx = ix - fx0, fy = iy - fy0, fz = iz - fz0;
    float wx0 = 1.f - fx, wy0 = 1.f - fy, wz0 = 1.f - fz;

    int x0c = min(max(x0, 0), 31), x1c = min(max(x0 + 1, 0), 31);
    int y0c = min(max(y0, 0), 31), y1c = min(max(y0 + 1, 0), 31);
    int z0c = min(max(z0, 0), 7),  z1c = min(max(z0 + 1, 0), 7);
    bool vx0 = ((unsigned)x0 < 32u), vx1 = ((unsigned)(x0 + 1) < 32u);
    bool vy0 = ((unsigned)y0 < 32u), vy1 = ((unsigned)(y0 + 1) < 32u);
    bool vz0 = ((unsigned)z0 < 8u),  vz1 = ((unsigned)(z0 + 1) < 8u);

    int  o0 = (z0c*32 + y0c)*32 + x0c;
    int  o1 = (z0c*32 + y0c)*32 + x1c;
    int  o2 = (z0c*32 + y1c)*32 + x0c;
    int  o3 = (z0c*32 + y1c)*32 + x1c;
    int  o4 = (z1c*32 + y0c)*32 + x0c;
    int  o5 = (z1c*32 + y0c)*32 + x1c;
    int  o6 = (z1c*32 + y1c)*32 + x0c;
    int  o7 = (z1c*32 + y1c)*32 + x1c;
    float t0 = (vz0 && vy0 && vx0) ? wz0*wy0*wx0 : 0.f;
    float t1 = (vz0 && vy0 && vx1) ? wz0*wy0*fx  : 0.f;
    float t2 = (vz0 && vy1 && vx0) ? wz0*fy*wx0  : 0.f;
    float t3 = (vz0 && vy1 && vx1) ? wz0*fy*fx   : 0.f;
    float t4 = (vz1 && vy0 && vx0) ? fz*wy0*wx0  : 0.f;
    float t5 = (vz1 && vy0 && vx1) ? fz*wy0*fx   : 0.f;
    float t6 = (vz1 && vy1 && vx0) ? fz*fy*wx0   : 0.f;
    float t7 = (vz1 && vy1 && vx1) ? fz*fy*fx    : 0.f;

    const float* yb = y + (size_t)n*CYC*PY;
    float* ob = out + (size_t)n*CYC*PX + p;
    #pragma unroll 4
    for (int c = 0; c < 128; c++) {
        const float* yc = yb + (size_t)c*PY;
        float acc;
        acc = t0 * __ldg(yc + o0);
        acc = fmaf(t1, __ldg(yc + o1), acc);
        acc = fmaf(t2, __ldg(yc + o2), acc);
        acc = fmaf(t3, __ldg(yc + o3), acc);
        acc = fmaf(t4, __ldg(yc + o4), acc);
        acc = fmaf(t5, __ldg(yc + o5), acc);
        acc = fmaf(t6, __ldg(yc + o6), acc);
        acc = fmaf(t7, __ldg(yc + o7), acc);
        ob[(size_t)c*PX] = acc;
    }
}

// --------------------------------- launch ----------------------------------
extern "C" void kernel_launch(void* const* d_in, const int* in_sizes, int n_in,
                              void* d_out, int out_size) {
    const float* x     = (const float*)d_in[0];
    const float* y     = (const float*)d_in[1];
    const float* wdh   = (const float*)d_in[2];
    const float* wdl   = (const float*)d_in[3];
    const float* wflow = (const float*)d_in[4];
    const float* wa    = (const float*)d_in[5];
    const float* wc    = (const float*)d_in[6];
    float* out = (float*)d_out;

    k_xmean<<<NB*CXC, 256>>>(x);
    k_prep<<<NB, 64>>>(wdl, wa, wc);
    k_hf<<<dim3(PY/128, NB), 128>>>(y, wdh);
    k_low<<<dim3(PX/128, NB), 128>>>(x);
    k_up<<<(NB*CO*PX)/256, 256>>>();
    k_conv3<<<dim3(16, 8, NB), dim3(32, 8, 2)>>>(wflow);
    k_sample<<<dim3(PX/128, NB), 128>>>(y, out);
}

// round 2
// speedup vs baseline: 1.6522x; 1.6522x over previous
#include <cuda_runtime.h>
#include <math.h>

#define NB 2
#define CXC 64
#define CYC 128
#define CO  64
#define DD  16
#define HH  64
#define WW  64
#define PX  (DD*HH*WW)    /* 65536 */
#define PY  (8*32*32)     /* 8192  */

// ---------------- scratch (device globals; no allocation) ----------------
__device__ float g_xmean[NB*CXC];
__device__ float g_w1[NB*64*108];                // folded x-path conv weights (padded layout)
__device__ float g_hf[NB*CO*PY];                 // 4 MB
__device__ float g_hfup[(size_t)NB*CO*PX];       // 33 MB
__device__ float g_flowp[4][NB*3*PX];            // 6.3 MB partial flows

// ---------------- K1: xmean[n][c] = mean over spatial of x ----------------
__global__ void k_xmean(const float* __restrict__ x) {
    int nc = blockIdx.x;                     // 0..127
    const float4* p = (const float4*)(x + (size_t)nc * PX);
    float s = 0.f;
    for (int i = threadIdx.x; i < PX/4; i += 256) {
        float4 v = p[i];
        s += (v.x + v.y) + (v.z + v.w);
    }
    #pragma unroll
    for (int o = 16; o > 0; o >>= 1) s += __shfl_xor_sync(0xffffffffu, s, o);
    __shared__ float sm[8];
    if ((threadIdx.x & 31) == 0) sm[threadIdx.x >> 5] = s;
    __syncthreads();
    if (threadIdx.x < 8) {
        float t = sm[threadIdx.x];
        #pragma unroll
        for (int o = 4; o > 0; o >>= 1) t += __shfl_xor_sync(0xffu, t, o, 8);
        if (threadIdx.x == 0) g_xmean[nc] = t * (1.f / PX);
    }
}

// ---- K2: fold SE attention + 1x1 conv + flow-conv low half into W1_n ----
// M_n[c][i] = sum_k wc[c,k]*scale[k]*wdl[k,i]
// W1_n[i][tap_slot(o3,tap)] = sum_c wflow[o3,64+c,tap] * M_n[c][i]
__global__ void k_prep(const float* __restrict__ wdl,
                       const float* __restrict__ wa,
                       const float* __restrict__ wc,
                       const float* __restrict__ wflow) {
    int n = blockIdx.x, t = threadIdx.x;     // 256 threads
    __shared__ float xm[64], pooled[64], scale[64];
    __shared__ float M[64][64];
    if (t < 64) xm[t] = g_xmean[n*64 + t];
    __syncthreads();
    if (t < 64) {
        float s = 0.f;
        for (int i = 0; i < 64; i++) s += wdl[t*64 + i] * xm[i];
        pooled[t] = s;
    }
    __syncthreads();
    if (t < 64) {
        float a = 0.f;
        for (int i = 0; i < 64; i++) a += wa[t*64 + i] * pooled[i];
        scale[t] = 1.f + 1.f / (1.f + expf(-a));
    }
    __syncthreads();
    for (int idx = t; idx < 4096; idx += 256) {
        int o = idx >> 6, i = idx & 63;
        float acc = 0.f;
        for (int c = 0; c < 64; c++) acc += wc[o*64 + c] * scale[c] * wdl[c*64 + i];
        M[o][i] = acc;
    }
    __syncthreads();
    for (int idx = t; idx < 64*81; idx += 256) {
        int i = idx / 81; int r = idx % 81; int tap = r / 3; int o3 = r % 3;
        float acc = 0.f;
        for (int c = 0; c < 64; c++)
            acc += wflow[o3*(128*27) + (64 + c)*27 + tap] * M[c][i];
        int kd = tap/9, kh = (tap/3)%3, kw = tap%3;
        g_w1[n*64*108 + i*108 + (kd*3 + kh)*12 + kw*3 + o3] = acc;
    }
}

// ---------------- K3: hf_small = w_down_h @ y  (128 -> 64) ----------------
// grid (PY/128, NB, 4 output-channel groups of 16)
__global__ void k_hf(const float* __restrict__ y, const float* __restrict__ wdh) {
    __shared__ float wT[128][16];            // wT[i][o_local]
    int tid = threadIdx.x;                   // 128
    int og = blockIdx.z;
    for (int idx = tid; idx < 128*16; idx += 128) {
        int ol = idx >> 7, i = idx & 127;
        wT[i][ol] = wdh[(og*16 + ol)*128 + i];
    }
    __syncthreads();
    int n = blockIdx.y;
    int p = blockIdx.x*128 + tid;
    const float* yp = y + (size_t)n*CYC*PY + p;
    float acc[16];
    #pragma unroll
    for (int o = 0; o < 16; o++) acc[o] = 0.f;
    for (int i = 0; i < 128; i++) {
        float v = yp[(size_t)i*PY];
        #pragma unroll
        for (int o4 = 0; o4 < 4; o4++) {
            float4 w4 = *(const float4*)&wT[i][o4*4];
            acc[o4*4+0] = fmaf(w4.x, v, acc[o4*4+0]);
            acc[o4*4+1] = fmaf(w4.y, v, acc[o4*4+1]);
            acc[o4*4+2] = fmaf(w4.z, v, acc[o4*4+2]);
            acc[o4*4+3] = fmaf(w4.w, v, acc[o4*4+3]);
        }
    }
    float* op = g_hf + (size_t)(n*CO + og*16)*PY + p;
    #pragma unroll
    for (int o = 0; o < 16; o++) op[(size_t)o*PY] = acc[o];
}

// ------ K4: trilinear upsample (align_corners) hf -> g_hfup ----------------
__global__ void k_up() {
    int idx = blockIdx.x*256 + threadIdx.x;  // over NB*CO*PX
    int w = idx & 63;
    int h = (idx >> 6) & 63;
    int d = (idx >> 12) & 15;
    float pw = w * (31.f/63.f);
    float ph = h * (31.f/63.f);
    float pd = d * (7.f/15.f);
    int w0 = (int)pw; if (w0 > 31) w0 = 31;
    int h0 = (int)ph; if (h0 > 31) h0 = 31;
    int d0 = (int)pd; if (d0 > 7)  d0 = 7;
    float fw = pw - w0, fh = ph - h0, fd = pd - d0;
    int w1 = min(w0 + 1, 31), h1 = min(h0 + 1, 31), d1 = min(d0 + 1, 7);
    const float* hp = g_hf + (size_t)(idx >> 16)*PY;   // (n*CO + c) slab
    float v000 = __ldg(hp + (d0*32 + h0)*32 + w0);
    float v001 = __ldg(hp + (d0*32 + h0)*32 + w1);
    float v010 = __ldg(hp + (d0*32 + h1)*32 + w0);
    float v011 = __ldg(hp + (d0*32 + h1)*32 + w1);
    float v100 = __ldg(hp + (d1*32 + h0)*32 + w0);
    float v101 = __ldg(hp + (d1*32 + h0)*32 + w1);
    float v110 = __ldg(hp + (d1*32 + h1)*32 + w0);
    float v111 = __ldg(hp + (d1*32 + h1)*32 + w1);
    float c00 = v000*(1.f-fw) + v001*fw;
    float c01 = v010*(1.f-fw) + v011*fw;
    float c10 = v100*(1.f-fw) + v101*fw;
    float c11 = v110*(1.f-fw) + v111*fw;
    float c0  = c00*(1.f-fh) + c01*fh;
    float c1  = c10*(1.f-fh) + c11*fh;
    g_hfup[idx] = c0*(1.f-fd) + c1*fd;
}

// ------------- K5: 3x3x3 conv, 4 channel-groups of 32 -> partial flow ------
// block (32,8,2): output tile (w=32,h=8,d=2); smem input tile 4x10x34 dbl-buf.
#define TROW 34
#define TPLANE 340
#define TSIZE 1360
__global__ void k_conv3(const float* __restrict__ x, const float* __restrict__ wflow) {
    __shared__ __align__(16) float tile[2][TSIZE];
    __shared__ __align__(16) float wsm[32*108];
    int bz = blockIdx.z;
    int n = bz >> 2, g = bz & 3;
    int d0 = blockIdx.y * 2;
    int h0 = (blockIdx.x >> 1) * 8;
    int w0 = (blockIdx.x & 1) * 32;
    int tx = threadIdx.x, ty = threadIdx.y, tz = threadIdx.z;
    int tid = (tz*8 + ty)*32 + tx;            // 0..511

    const float* inb = (g < 2) ? (x + (size_t)(n*64 + g*32)*PX)
                               : (g_hfup + (size_t)(n*64 + (g-2)*32)*PX);
    // stage weights for this group's 32 channels
    if (g < 2) {
        const float* src = g_w1 + (size_t)(n*64 + g*32)*108;
        for (int idx = tid; idx < 32*108; idx += 512) wsm[idx] = src[idx];
    } else {
        for (int idx = tid; idx < 32*81; idx += 512) {
            int oc = idx % 3; int r = idx / 3; int tap = r % 27; int cil = r / 27;
            int kd = tap/9, kh = (tap/3)%3, kw = tap%3;
            wsm[cil*108 + (kd*3 + kh)*12 + kw*3 + oc] =
                wflow[oc*(128*27) + ((g-2)*32 + cil)*27 + tap];
        }
    }

    // precompute the 3 load slots this thread fills in the tile
    int e0 = tid, e1 = tid + 512, e2 = tid + 1024;
    int off0 = 0, off1 = 0, off2 = 0;
    bool ok0 = false, ok1 = false, ok2 = false;
    bool live2 = (e2 < TSIZE);
    {
        int e = e0;
        int zz = e / TPLANE; int rr = e - zz*TPLANE; int yy = rr / TROW; int xx = rr - yy*TROW;
        int gz = d0 - 1 + zz, gy = h0 - 1 + yy, gx = w0 - 1 + xx;
        ok0 = ((unsigned)gz < 16u) && ((unsigned)gy < 64u) && ((unsigned)gx < 64u);
        off0 = (gz*64 + gy)*64 + gx;
        e = e1;
        zz = e / TPLANE; rr = e - zz*TPLANE; yy = rr / TROW; xx = rr - yy*TROW;
        gz = d0 - 1 + zz; gy = h0 - 1 + yy; gx = w0 - 1 + xx;
        ok1 = ((unsigned)gz < 16u) && ((unsigned)gy < 64u) && ((unsigned)gx < 64u);
        off1 = (gz*64 + gy)*64 + gx;
        if (live2) {
            e = e2;
            zz = e / TPLANE; rr = e - zz*TPLANE; yy = rr / TROW; xx = rr - yy*TROW;
            gz = d0 - 1 + zz; gy = h0 - 1 + yy; gx = w0 - 1 + xx;
            ok2 = ((unsigned)gz < 16u) && ((unsigned)gy < 64u) && ((unsigned)gx < 64u);
            off2 = (gz*64 + gy)*64 + gx;
        }
    }

    float a0 = 0.f, a1 = 0.f, a2 = 0.f;
    float r0, r1, r2;
    r0 = ok0 ? __ldg(inb + off0) : 0.f;
    r1 = ok1 ? __ldg(inb + off1) : 0.f;
    r2 = (live2 && ok2) ? __ldg(inb + off2) : 0.f;

    for (int cil = 0; cil < 32; cil++) {
        float* tb = tile[cil & 1];
        tb[e0] = r0; tb[e1] = r1;
        if (live2) tb[e2] = r2;
        __syncthreads();
        if (cil + 1 < 32) {
            const float* cb = inb + (size_t)(cil + 1)*PX;
            r0 = ok0 ? __ldg(cb + off0) : 0.f;
            r1 = ok1 ? __ldg(cb + off1) : 0.f;
            r2 = (live2 && ok2) ? __ldg(cb + off2) : 0.f;
        }
        const float* wp = wsm + cil*108;
        const float* tbase = tb + tz*TPLANE + ty*TROW + tx;
        #pragma unroll
        for (int kd = 0; kd < 3; kd++) {
            #pragma unroll
            for (int kh = 0; kh < 3; kh++) {
                const float* row = tbase + kd*TPLANE + kh*TROW;
                const float4 q0 = *(const float4*)(wp + (kd*3 + kh)*12);
                const float4 q1 = *(const float4*)(wp + (kd*3 + kh)*12 + 4);
                const float  q8 = wp[(kd*3 + kh)*12 + 8];
                float v0 = row[0], v1 = row[1], v2 = row[2];
                a0 = fmaf(q0.x, v0, a0); a1 = fmaf(q0.y, v0, a1); a2 = fmaf(q0.z, v0, a2);
                a0 = fmaf(q0.w, v1, a0); a1 = fmaf(q1.x, v1, a1); a2 = fmaf(q1.y, v1, a2);
                a0 = fmaf(q1.z, v2, a0); a1 = fmaf(q1.w, v2, a1); a2 = fmaf(q8,   v2, a2);
            }
        }
        __syncthreads();
    }
    size_t po = ((size_t)(d0 + tz)*64 + (h0 + ty))*64 + (w0 + tx);
    float* fp = g_flowp[g] + (size_t)n*3*PX + po;
    fp[0]      = a0;
    fp[PX]     = a1;
    fp[2*PX]   = a2;
}

// -------- K6: flow warp + trilinear grid sample (zeros padding) ------------
__global__ void k_sample(const float* __restrict__ y, float* __restrict__ out) {
    int p = blockIdx.x*128 + threadIdx.x;     // 0..65535
    int n = blockIdx.y;
    int w = p & 63, h = (p >> 6) & 63, d = p >> 12;
    size_t fo = (size_t)n*3*PX + p;
    float f0 = g_flowp[0][fo]        + g_flowp[1][fo]        + g_flowp[2][fo]        + g_flowp[3][fo];
    float f1 = g_flowp[0][fo + PX]   + g_flowp[1][fo + PX]   + g_flowp[2][fo + PX]   + g_flowp[3][fo + PX];
    float f2 = g_flowp[0][fo + 2*PX] + g_flowp[1][fo + 2*PX] + g_flowp[2][fo + 2*PX] + g_flowp[3][fo + 2*PX];
    float gx = (w + f0) * (1.f/64.f);
    float gy = (h + f1) * (1.f/64.f);
    float gz = (d + f2) * (1.f/16.f);
    float ix = ((gx + 1.f)*32.f - 1.f)*0.5f;
    float iy = ((gy + 1.f)*32.f - 1.f)*0.5f;
    float iz = ((gz + 1.f)*8.f  - 1.f)*0.5f;
    float fx0 = floorf(ix), fy0 = floorf(iy), fz0 = floorf(iz);
    int x0 = (int)fx0, y0 = (int)fy0, z0 = (int)fz0;
    float fx = ix - fx0, fy = iy - fy0, fz = iz - fz0;
    float wx0 = 1.f - fx, wy0 = 1.f - fy, wz0 = 1.f - fz;

    int x0c = min(max(x0, 0), 31), x1c = min(max(x0 + 1, 0), 31);
    int y0c = min(max(y0, 0), 31), y1c = min(max(y0 + 1, 0), 31);
    int z0c = min(max(z0, 0), 7),  z1c = min(max(z0 + 1, 0), 7);
    bool vx0 = ((unsigned)x0 < 32u), vx1 = ((unsigned)(x0 + 1) < 32u);
    bool vy0 = ((unsigned)y0 < 32u), vy1 = ((unsigned)(y0 + 1) < 32u);
    bool vz0 = ((unsigned)z0 < 8u),  vz1 = ((unsigned)(z0 + 1) < 8u);

    int  o0 = (z0c*32 + y0c)*32 + x0c;
    int  o1 = (z0c*32 + y0c)*32 + x1c;
    int  o2 = (z0c*32 + y1c)*32 + x0c;
    int  o3 = (z0c*32 + y1c)*32 + x1c;
    int  o4 = (z1c*32 + y0c)*32 + x0c;
    int  o5 = (z1c*32 + y0c)*32 + x1c;
    int  o6 = (z1c*32 + y1c)*32 + x0c;
    int  o7 = (z1c*32 + y1c)*32 + x1c;
    float t0 = (vz0 && vy0 && vx0) ? wz0*wy0*wx0 : 0.f;
    float t1 = (vz0 && vy0 && vx1) ? wz0*wy0*fx  : 0.f;
    float t2 = (vz0 && vy1 && vx0) ? wz0*fy*wx0  : 0.f;
    float t3 = (vz0 && vy1 && vx1) ? wz0*fy*fx   : 0.f;
    float t4 = (vz1 && vy0 && vx0) ? fz*wy0*wx0  : 0.f;
    float t5 = (vz1 && vy0 && vx1) ? fz*wy0*fx   : 0.f;
    float t6 = (vz1 && vy1 && vx0) ? fz*fy*wx0   : 0.f;
    float t7 = (vz1 && vy1 && vx1) ? fz*fy*fx    : 0.f;

    const float* yb = y + (size_t)n*CYC*PY;
    float* ob = out + (size_t)n*CYC*PX + p;
    #pragma unroll 4
    for (int c = 0; c < 128; c++) {
        const float* yc = yb + (size_t)c*PY;
        float acc;
        acc = t0 * __ldg(yc + o0);
        acc = fmaf(t1, __ldg(yc + o1), acc);
        acc = fmaf(t2, __ldg(yc + o2), acc);
        acc = fmaf(t3, __ldg(yc + o3), acc);
        acc = fmaf(t4, __ldg(yc + o4), acc);
        acc = fmaf(t5, __ldg(yc + o5), acc);
        acc = fmaf(t6, __ldg(yc + o6), acc);
        acc = fmaf(t7, __ldg(yc + o7), acc);
        ob[(size_t)c*PX] = acc;
    }
}

// --------------------------------- launch ----------------------------------
extern "C" void kernel_launch(void* const* d_in, const int* in_sizes, int n_in,
                              void* d_out, int out_size) {
    const float* x     = (const float*)d_in[0];
    const float* y     = (const float*)d_in[1];
    const float* wdh   = (const float*)d_in[2];
    const float* wdl   = (const float*)d_in[3];
    const float* wflow = (const float*)d_in[4];
    const float* wa    = (const float*)d_in[5];
    const float* wc    = (const float*)d_in[6];
    float* out = (float*)d_out;

    k_xmean<<<NB*CXC, 256>>>(x);
    k_prep<<<NB, 256>>>(wdl, wa, wc, wflow);
    k_hf<<<dim3(PY/128, NB, 4), 128>>>(y, wdh);
    k_up<<<(NB*CO*PX)/256, 256>>>();
    k_conv3<<<dim3(16, 8, NB*4), dim3(32, 8, 2)>>>(x, wflow);
    k_sample<<<dim3(PX/128, NB), 128>>>(y, out);
}

// round 3
// speedup vs baseline: 1.8200x; 1.1016x over previous
#include <cuda_runtime.h>
#include <math.h>

#define NB 2
#define CXC 64
#define CYC 128
#define CO  64
#define DD  16
#define HH  64
#define WW  64
#define PX  (DD*HH*WW)    /* 65536 */
#define PY  (8*32*32)     /* 8192  */

// packed f32x2 FMA (Blackwell): one instr = 2 fp32 FMA
#define FMA2(acc, a, b) asm("fma.rn.f32x2 %0, %1, %2, %0;" : "+l"(acc) : "l"(a), "l"(b))

union F2U { float2 f; unsigned long long u; };
union F4U { float4 f; unsigned long long u[2]; };

// ---------------- scratch (device globals; no allocation) ----------------
__device__ float g_xmean[NB*CXC];
__device__ float g_w1[NB*64*180];                // folded x-path weights, dup-pair layout
__device__ float g_hf[NB*CO*PY];                 // 4 MB
__device__ float g_hfup[(size_t)NB*CO*PX];       // 33 MB
__device__ float g_flowp[8][NB*3*PX];            // partial flows per channel-group

// ---------------- K1: xmean[n][c] = mean over spatial of x ----------------
__global__ void k_xmean(const float* __restrict__ x) {
    int nc = blockIdx.x;                     // 0..127
    const float4* p = (const float4*)(x + (size_t)nc * PX);
    float s = 0.f;
    #pragma unroll 4
    for (int i = threadIdx.x; i < PX/4; i += 256) {
        float4 v = p[i];
        s += (v.x + v.y) + (v.z + v.w);
    }
    #pragma unroll
    for (int o = 16; o > 0; o >>= 1) s += __shfl_xor_sync(0xffffffffu, s, o);
    __shared__ float sm[8];
    if ((threadIdx.x & 31) == 0) sm[threadIdx.x >> 5] = s;
    __syncthreads();
    if (threadIdx.x < 8) {
        float t = sm[threadIdx.x];
        #pragma unroll
        for (int o = 4; o > 0; o >>= 1) t += __shfl_xor_sync(0xffu, t, o, 8);
        if (threadIdx.x == 0) g_xmean[nc] = t * (1.f / PX);
    }
}

// ---- K2: fold SE attention + 1x1 conv + flow-conv low half into W1_n ----
// M_n[c][i] = sum_k wc[c,k]*scale[k]*wdl[k,i]
// g_w1 layout: [n][i][row(kd*3+kh)][20] with dup pairs at 2*(kw*3+o3)
__global__ void k_prep(const float* __restrict__ wdl,
                       const float* __restrict__ wa,
                       const float* __restrict__ wc,
                       const float* __restrict__ wflow) {
    int n = blockIdx.x, t = threadIdx.x;     // 256 threads
    __shared__ float xm[64], pooled[64], scale[64];
    __shared__ float M[64][64];
    if (t < 64) xm[t] = g_xmean[n*64 + t];
    __syncthreads();
    if (t < 64) {
        float s = 0.f;
        for (int i = 0; i < 64; i++) s += wdl[t*64 + i] * xm[i];
        pooled[t] = s;
    }
    __syncthreads();
    if (t < 64) {
        float a = 0.f;
        for (int i = 0; i < 64; i++) a += wa[t*64 + i] * pooled[i];
        scale[t] = 1.f + 1.f / (1.f + expf(-a));
    }
    __syncthreads();
    for (int idx = t; idx < 4096; idx += 256) {
        int o = idx >> 6, i = idx & 63;
        float acc = 0.f;
        for (int c = 0; c < 64; c++) acc += wc[o*64 + c] * scale[c] * wdl[c*64 + i];
        M[o][i] = acc;
    }
    __syncthreads();
    for (int idx = t; idx < 64*81; idx += 256) {
        int i = idx / 81; int r = idx % 81; int tap = r / 3; int o3 = r % 3;
        float acc = 0.f;
        for (int c = 0; c < 64; c++)
            acc += wflow[o3*(128*27) + (64 + c)*27 + tap] * M[c][i];
        int kd = tap/9, kh = (tap/3)%3, kw = tap%3;
        float* dst = g_w1 + (size_t)(n*64 + i)*180 + (kd*3 + kh)*20 + 2*(kw*3 + o3);
        dst[0] = acc; dst[1] = acc;
    }
}

// ---------------- K3: hf_small = w_down_h @ y  (128 -> 64) ----------------
__global__ void k_hf(const float* __restrict__ y, const float* __restrict__ wdh) {
    __shared__ float wT[128][16];            // wT[i][o_local]
    int tid = threadIdx.x;                   // 128
    int og = blockIdx.z;
    for (int idx = tid; idx < 128*16; idx += 128) {
        int ol = idx >> 7, i = idx & 127;
        wT[i][ol] = wdh[(og*16 + ol)*128 + i];
    }
    __syncthreads();
    int n = blockIdx.y;
    int p = blockIdx.x*128 + tid;
    const float* yp = y + (size_t)n*CYC*PY + p;
    float acc[16];
    #pragma unroll
    for (int o = 0; o < 16; o++) acc[o] = 0.f;
    for (int i = 0; i < 128; i++) {
        float v = yp[(size_t)i*PY];
        #pragma unroll
        for (int o4 = 0; o4 < 4; o4++) {
            float4 w4 = *(const float4*)&wT[i][o4*4];
            acc[o4*4+0] = fmaf(w4.x, v, acc[o4*4+0]);
            acc[o4*4+1] = fmaf(w4.y, v, acc[o4*4+1]);
            acc[o4*4+2] = fmaf(w4.z, v, acc[o4*4+2]);
            acc[o4*4+3] = fmaf(w4.w, v, acc[o4*4+3]);
        }
    }
    float* op = g_hf + (size_t)(n*CO + og*16)*PY + p;
    #pragma unroll
    for (int o = 0; o < 16; o++) op[(size_t)o*PY] = acc[o];
}

// ------ K4: trilinear upsample, 4 outputs/thread, shared source columns ----
__global__ void k_up() {
    int t = blockIdx.x*256 + threadIdx.x;    // over NB*CO*16*64*16
    int wg = (t & 15) << 2;                  // w start: 0,4,...,60
    int h  = (t >> 4) & 63;
    int d  = (t >> 10) & 15;
    int slab = t >> 14;                      // n*CO + c
    const float* hp = g_hf + (size_t)slab * PY;
    float ph = h * (31.f/63.f);
    float pd = d * (7.f/15.f);
    int h0 = (int)ph; float fh = ph - (float)h0; int h1 = min(h0 + 1, 31);
    int d0 = (int)pd; float fd = pd - (float)d0; int d1 = min(d0 + 1, 7);
    int xbase = (int)(wg * (31.f/63.f));
    const float* p00 = hp + (d0*32 + h0)*32;
    const float* p01 = hp + (d0*32 + h1)*32;
    const float* p10 = hp + (d1*32 + h0)*32;
    const float* p11 = hp + (d1*32 + h1)*32;
    float V[4];
    #pragma unroll
    for (int c2 = 0; c2 < 4; c2++) {
        int xc = min(xbase + c2, 31);
        float v00 = __ldg(p00 + xc), v01 = __ldg(p01 + xc);
        float v10 = __ldg(p10 + xc), v11 = __ldg(p11 + xc);
        float a = v00 + (v01 - v00)*fh;
        float b = v10 + (v11 - v10)*fh;
        V[c2] = a + (b - a)*fd;
    }
    float4 ov;
    float* po = (float*)&ov;
    #pragma unroll
    for (int i = 0; i < 4; i++) {
        float pw = (wg + i) * (31.f/63.f);
        int x0 = (int)pw; float fx = pw - (float)x0;
        int k = x0 - xbase;
        float va = (k == 0) ? V[0] : ((k == 1) ? V[1] : V[2]);
        float vb = (k == 0) ? V[1] : ((k == 1) ? V[2] : V[3]);
        po[i] = va + (vb - va)*fx;
    }
    *(float4*)(g_hfup + (size_t)slab*PX + ((d << 6) + h)*64 + wg) = ov;
}

// ------------- K5: 3x3x3 conv, f32x2-packed, 8 groups of 16 channels -------
// block (32,8,2): output tile (w=64 as 32 pairs, h=8, d=2)
// tile 4 x 10 x 66, double buffered; weights duplicated-pair smem layout.
#define TROW 66
#define TPLANE 660
#define TSIZE 2640
__global__ void __launch_bounds__(512, 2) k_conv3(const float* __restrict__ x,
                                                  const float* __restrict__ wflow) {
    __shared__ __align__(16) float tile[2][TSIZE];
    __shared__ __align__(16) float wsm[16*180];
    int bz = blockIdx.z;
    int n = bz >> 3, g = bz & 7;
    int d0 = blockIdx.y * 2;
    int h0 = blockIdx.x * 8;
    int tx = threadIdx.x, ty = threadIdx.y, tz = threadIdx.z;
    int tid = (tz*8 + ty)*32 + tx;            // 0..511

    const float* inb = (g < 4) ? (x + (size_t)(n*64 + g*16)*PX)
                               : (g_hfup + (size_t)(n*64 + (g-4)*16)*PX);
    // stage weights (dup-pair layout: [ch][row][20], pair j=(kw*3+o) at 2j)
    if (g < 4) {
        const float* src = g_w1 + (size_t)(n*64 + g*16)*180;
        for (int idx = tid; idx < 16*180; idx += 512) wsm[idx] = src[idx];
    } else {
        int cbase = (g - 4)*16;
        for (int idx = tid; idx < 16*81; idx += 512) {
            int ch = idx / 81; int r = idx % 81; int tap = r / 3; int o = r % 3;
            int kd = tap/9, kh = (tap/3)%3, kw = tap%3;
            float v = wflow[o*(128*27) + (cbase + ch)*27 + tap];
            int dst = ch*180 + (kd*3 + kh)*20 + 2*(kw*3 + o);
            wsm[dst] = v; wsm[dst + 1] = v;
        }
    }

    // tile fill slots: 6 per thread
    int   off[6]; bool ok[6];
    #pragma unroll
    for (int k = 0; k < 6; k++) {
        int e = tid + k*512;
        int zz = e / TPLANE; int rr = e - zz*TPLANE;
        int yy = rr / TROW;  int xx = rr - yy*TROW;
        int gz = d0 - 1 + zz, gy = h0 - 1 + yy, gx = xx - 1;
        bool live = (e < TSIZE);
        ok[k] = live && ((unsigned)gz < 16u) && ((unsigned)gy < 64u) && ((unsigned)gx < 64u);
        off[k] = (gz*64 + gy)*64 + gx;
    }
    bool live5 = (tid + 5*512) < TSIZE;

    unsigned long long acc0 = 0ULL, acc1 = 0ULL, acc2 = 0ULL;
    float r[6];
    #pragma unroll
    for (int k = 0; k < 6; k++) r[k] = ok[k] ? __ldg(inb + off[k]) : 0.f;
    {
        float* b0 = tile[0];
        #pragma unroll
        for (int k = 0; k < 5; k++) b0[tid + k*512] = r[k];
        if (live5) b0[tid + 5*512] = r[5];
    }
    __syncthreads();

    const int tb_off = tz*TPLANE + ty*TROW + 2*tx;
    for (int c = 0; c < 16; c++) {
        const float* tb = tile[c & 1];
        if (c < 15) {
            const float* cb = inb + (size_t)(c + 1)*PX;
            #pragma unroll
            for (int k = 0; k < 6; k++) r[k] = ok[k] ? __ldg(cb + off[k]) : 0.f;
        }
        const float* wp = wsm + c*180;
        #pragma unroll
        for (int kd = 0; kd < 3; kd++) {
            #pragma unroll
            for (int kh = 0; kh < 3; kh++) {
                const float* row = tb + tb_off + kd*TPLANE + kh*TROW;
                F2U A, B;
                A.f = *(const float2*)row;
                B.f = *(const float2*)(row + 2);
                unsigned long long mid;
                asm("mov.b64 %0, {%1, %2};" : "=l"(mid) : "f"(A.f.y), "f"(B.f.x));
                const float* wr = wp + (kd*3 + kh)*20;
                F4U wA, wB, wC, wD; F2U wE;
                wA.f = *(const float4*)(wr);
                wB.f = *(const float4*)(wr + 4);
                wC.f = *(const float4*)(wr + 8);
                wD.f = *(const float4*)(wr + 12);
                wE.f = *(const float2*)(wr + 16);
                FMA2(acc0, A.u,  wA.u[0]);
                FMA2(acc1, A.u,  wA.u[1]);
                FMA2(acc2, A.u,  wB.u[0]);
                FMA2(acc0, mid,  wB.u[1]);
                FMA2(acc1, mid,  wC.u[0]);
                FMA2(acc2, mid,  wC.u[1]);
                FMA2(acc0, B.u,  wD.u[0]);
                FMA2(acc1, B.u,  wD.u[1]);
                FMA2(acc2, B.u,  wE.u);
            }
        }
        if (c < 15) {
            float* nb2 = tile[(c + 1) & 1];
            #pragma unroll
            for (int k = 0; k < 5; k++) nb2[tid + k*512] = r[k];
            if (live5) nb2[tid + 5*512] = r[5];
        }
        __syncthreads();
    }

    size_t po = ((size_t)(d0 + tz)*64 + (h0 + ty))*64 + 2*tx;
    float* fp = g_flowp[g] + (size_t)n*3*PX + po;
    F2U s0, s1, s2;
    s0.u = acc0; s1.u = acc1; s2.u = acc2;
    *(float2*)(fp)          = s0.f;
    *(float2*)(fp + PX)     = s1.f;
    *(float2*)(fp + 2*PX)   = s2.f;
}

// -------- K6: flow warp + trilinear grid sample (zeros padding) ------------
__global__ void k_sample(const float* __restrict__ y, float* __restrict__ out) {
    int p = blockIdx.x*256 + threadIdx.x;     // 0..65535
    int n = blockIdx.y;
    int w = p & 63, h = (p >> 6) & 63, d = p >> 12;
    size_t fo = (size_t)n*3*PX + p;
    float f0 = 0.f, f1 = 0.f, f2 = 0.f;
    #pragma unroll
    for (int g = 0; g < 8; g++) {
        f0 += g_flowp[g][fo];
        f1 += g_flowp[g][fo + PX];
        f2 += g_flowp[g][fo + 2*PX];
    }
    float gx = (w + f0) * (1.f/64.f);
    float gy = (h + f1) * (1.f/64.f);
    float gz = (d + f2) * (1.f/16.f);
    float ix = ((gx + 1.f)*32.f - 1.f)*0.5f;
    float iy = ((gy + 1.f)*32.f - 1.f)*0.5f;
    float iz = ((gz + 1.f)*8.f  - 1.f)*0.5f;
    float fx0 = floorf(ix), fy0 = floorf(iy), fz0 = floorf(iz);
    int x0 = (int)fx0, y0 = (int)fy0, z0 = (int)fz0;
    float fx = ix - fx0, fy = iy - fy0, fz = iz - fz0;
    float wx0 = 1.f - fx, wy0 = 1.f - fy, wz0 = 1.f - fz;

    int x0c = min(max(x0, 0), 31), x1c = min(max(x0 + 1, 0), 31);
    int y0c = min(max(y0, 0), 31), y1c = min(max(y0 + 1, 0), 31);
    int z0c = min(max(z0, 0), 7),  z1c = min(max(z0 + 1, 0), 7);
    bool vx0 = ((unsigned)x0 < 32u), vx1 = ((unsigned)(x0 + 1) < 32u);
    bool vy0 = ((unsigned)y0 < 32u), vy1 = ((unsigned)(y0 + 1) < 32u);
    bool vz0 = ((unsigned)z0 < 8u),  vz1 = ((unsigned)(z0 + 1) < 8u);

    int  o0 = (z0c*32 + y0c)*32 + x0c;
    int  o1 = (z0c*32 + y0c)*32 + x1c;
    int  o2 = (z0c*32 + y1c)*32 + x0c;
    int  o3 = (z0c*32 + y1c)*32 + x1c;
    int  o4 = (z1c*32 + y0c)*32 + x0c;
    int  o5 = (z1c*32 + y0c)*32 + x1c;
    int  o6 = (z1c*32 + y1c)*32 + x0c;
    int  o7 = (z1c*32 + y1c)*32 + x1c;
    float t0 = (vz0 && vy0 && vx0) ? wz0*wy0*wx0 : 0.f;
    float t1 = (vz0 && vy0 && vx1) ? wz0*wy0*fx  : 0.f;
    float t2 = (vz0 && vy1 && vx0) ? wz0*fy*wx0  : 0.f;
    float t3 = (vz0 && vy1 && vx1) ? wz0*fy*fx   : 0.f;
    float t4 = (vz1 && vy0 && vx0) ? fz*wy0*wx0  : 0.f;
    float t5 = (vz1 && vy0 && vx1) ? fz*wy0*fx   : 0.f;
    float t6 = (vz1 && vy1 && vx0) ? fz*fy*wx0   : 0.f;
    float t7 = (vz1 && vy1 && vx1) ? fz*fy*fx    : 0.f;

    const float* yb = y + (size_t)n*CYC*PY;
    float* ob = out + (size_t)n*CYC*PX + p;
    #pragma unroll 4
    for (int c = 0; c < 128; c++) {
        const float* yc = yb + (size_t)c*PY;
        float acc;
        acc = t0 * __ldg(yc + o0);
        acc = fmaf(t1, __ldg(yc + o1), acc);
        acc = fmaf(t2, __ldg(yc + o2), acc);
        acc = fmaf(t3, __ldg(yc + o3), acc);
        acc = fmaf(t4, __ldg(yc + o4), acc);
        acc = fmaf(t5, __ldg(yc + o5), acc);
        acc = fmaf(t6, __ldg(yc + o6), acc);
        acc = fmaf(t7, __ldg(yc + o7), acc);
        ob[(size_t)c*PX] = acc;
    }
}

// --------------------------------- launch ----------------------------------
extern "C" void kernel_launch(void* const* d_in, const int* in_sizes, int n_in,
                              void* d_out, int out_size) {
    const float* x     = (const float*)d_in[0];
    const float* y     = (const float*)d_in[1];
    const float* wdh   = (const float*)d_in[2];
    const float* wdl   = (const float*)d_in[3];
    const float* wflow = (const float*)d_in[4];
    const float* wa    = (const float*)d_in[5];
    const float* wc    = (const float*)d_in[6];
    float* out = (float*)d_out;

    k_xmean<<<NB*CXC, 256>>>(x);
    k_prep<<<NB, 256>>>(wdl, wa, wc, wflow);
    k_hf<<<dim3(PY/128, NB, 4), 128>>>(y, wdh);
    k_up<<<(NB*CO*PX/4)/256, 256>>>();
    k_conv3<<<dim3(8, 8, NB*8), dim3(32, 8, 2)>>>(x, wflow);
    k_sample<<<dim3(PX/256, NB), 256>>>(y, out);
}

// round 4
// speedup vs baseline: 2.1480x; 1.1802x over previous
#include <cuda_runtime.h>
#include <math.h>

#define NB 2
#define CXC 64
#define CYC 128
#define CO  64
#define DD  16
#define HH  64
#define WW  64
#define PX  (DD*HH*WW)    /* 65536 */
#define PY  (8*32*32)     /* 8192  */

// packed f32x2 FMA (Blackwell): one instr = 2 fp32 FMA
#define FMA2(acc, a, b) asm("fma.rn.f32x2 %0, %1, %2, %0;" : "+l"(acc) : "l"(a), "l"(b))

union F2U { float2 f; unsigned long long u; };
union F4U { float4 f; unsigned long long u[2]; };

// ---------------- scratch (device globals; no allocation) ----------------
__device__ float g_xmean[NB*CXC];
__device__ float g_w1[NB*64*180];                // folded x-path weights, dup-pair layout
__device__ float g_hf[NB*CO*PY];                 // 4 MB
__device__ float g_hfup[(size_t)NB*CO*PX];       // 33 MB
__device__ float g_flowp[8][NB*3*PX];            // partial flows per channel-group
__device__ float g_yT[(size_t)NB*PY*CYC];        // 8 MB  y transposed to [n][p][c]

// ===== K1 (fused): hf 1x1 conv  |  xmean  |  y transpose ====================
__global__ void k_pre(const float* __restrict__ y,
                      const float* __restrict__ wdh,
                      const float* __restrict__ x) {
    __shared__ float sh[2112];                   // max(wT 2048, trans 32*33=1056)
    int b = blockIdx.x;
    int tid = threadIdx.x;                       // 256

    if (b < 256) {
        // ---- hf: g_hf[n][og*16+o][p] = sum_i wdh[og*16+o][i] * y[n][i][p]
        int n  = b >> 7;
        int r  = b & 127;
        int og = r >> 5;
        int pb = r & 31;
        float (*wT)[16] = (float(*)[16])sh;      // wT[i][o_local]
        for (int idx = tid; idx < 128*16; idx += 256) {
            int ol = idx >> 7, i = idx & 127;
            wT[i][ol] = wdh[(og*16 + ol)*128 + i];
        }
        __syncthreads();
        int p = pb*256 + tid;
        const float* yp = y + (size_t)n*CYC*PY + p;
        float acc[16];
        #pragma unroll
        for (int o = 0; o < 16; o++) acc[o] = 0.f;
        for (int i = 0; i < 128; i++) {
            float v = yp[(size_t)i*PY];
            #pragma unroll
            for (int o4 = 0; o4 < 4; o4++) {
                float4 w4 = *(const float4*)&wT[i][o4*4];
                acc[o4*4+0] = fmaf(w4.x, v, acc[o4*4+0]);
                acc[o4*4+1] = fmaf(w4.y, v, acc[o4*4+1]);
                acc[o4*4+2] = fmaf(w4.z, v, acc[o4*4+2]);
                acc[o4*4+3] = fmaf(w4.w, v, acc[o4*4+3]);
            }
        }
        float* op = g_hf + (size_t)(n*CO + og*16)*PY + p;
        #pragma unroll
        for (int o = 0; o < 16; o++) op[(size_t)o*PY] = acc[o];
    } else if (b < 384) {
        // ---- xmean over x[nc][:]
        int nc = b - 256;
        const float4* p4 = (const float4*)(x + (size_t)nc * PX);
        float s = 0.f;
        #pragma unroll 4
        for (int i = tid; i < PX/4; i += 256) {
            float4 v = p4[i];
            s += (v.x + v.y) + (v.z + v.w);
        }
        #pragma unroll
        for (int o = 16; o > 0; o >>= 1) s += __shfl_xor_sync(0xffffffffu, s, o);
        if ((tid & 31) == 0) sh[tid >> 5] = s;
        __syncthreads();
        if (tid < 8) {
            float t = sh[tid];
            #pragma unroll
            for (int o = 4; o > 0; o >>= 1) t += __shfl_xor_sync(0xffu, t, o, 8);
            if (tid == 0) g_xmean[nc] = t * (1.f / PX);
        }
    } else {
        // ---- transpose y[n][c][pp] -> g_yT[n][pp][c], 32x32 tiles
        int bb = b - 384;                        // 0..2047
        int n  = bb >> 10;
        int r  = bb & 1023;
        int pt = r >> 2;                         // 0..255
        int ct = r & 3;                          // 0..3
        int tx = tid & 31, ty = tid >> 5;        // ty 0..7
        const float* yb = y + (size_t)n*CYC*PY;
        #pragma unroll
        for (int k = 0; k < 4; k++) {
            int cl = ty + k*8;
            sh[cl*33 + tx] = yb[(size_t)(ct*32 + cl)*PY + pt*32 + tx];
        }
        __syncthreads();
        float* ob = g_yT + ((size_t)n*PY)*CYC;
        #pragma unroll
        for (int k = 0; k < 4; k++) {
            int pl = ty + k*8;
            ob[(size_t)(pt*32 + pl)*CYC + ct*32 + tx] = sh[tx*33 + pl];
        }
    }
}

// ---- K2: fold SE attention + 1x1 conv + flow-conv low half into W1_n ----
__global__ void k_prep(const float* __restrict__ wdl,
                       const float* __restrict__ wa,
                       const float* __restrict__ wc,
                       const float* __restrict__ wflow) {
    int n = blockIdx.x, t = threadIdx.x;     // 256 threads
    __shared__ float xm[64], pooled[64], scale[64];
    __shared__ float M[64][64];
    if (t < 64) xm[t] = g_xmean[n*64 + t];
    __syncthreads();
    if (t < 64) {
        float s = 0.f;
        for (int i = 0; i < 64; i++) s += wdl[t*64 + i] * xm[i];
        pooled[t] = s;
    }
    __syncthreads();
    if (t < 64) {
        float a = 0.f;
        for (int i = 0; i < 64; i++) a += wa[t*64 + i] * pooled[i];
        scale[t] = 1.f + 1.f / (1.f + expf(-a));
    }
    __syncthreads();
    for (int idx = t; idx < 4096; idx += 256) {
        int o = idx >> 6, i = idx & 63;
        float acc = 0.f;
        for (int c = 0; c < 64; c++) acc += wc[o*64 + c] * scale[c] * wdl[c*64 + i];
        M[o][i] = acc;
    }
    __syncthreads();
    for (int idx = t; idx < 64*81; idx += 256) {
        int i = idx / 81; int r = idx % 81; int tap = r / 3; int o3 = r % 3;
        float acc = 0.f;
        for (int c = 0; c < 64; c++)
            acc += wflow[o3*(128*27) + (64 + c)*27 + tap] * M[c][i];
        int kd = tap/9, kh = (tap/3)%3, kw = tap%3;
        float* dst = g_w1 + (size_t)(n*64 + i)*180 + (kd*3 + kh)*20 + 2*(kw*3 + o3);
        dst[0] = acc; dst[1] = acc;
    }
}

// ------ K3: trilinear upsample, 4 outputs/thread, shared source columns ----
__global__ void k_up() {
    int t = blockIdx.x*256 + threadIdx.x;    // over NB*CO*16*64*16
    int wg = (t & 15) << 2;                  // w start: 0,4,...,60
    int h  = (t >> 4) & 63;
    int d  = (t >> 10) & 15;
    int slab = t >> 14;                      // n*CO + c
    const float* hp = g_hf + (size_t)slab * PY;
    float ph = h * (31.f/63.f);
    float pd = d * (7.f/15.f);
    int h0 = (int)ph; float fh = ph - (float)h0; int h1 = min(h0 + 1, 31);
    int d0 = (int)pd; float fd = pd - (float)d0; int d1 = min(d0 + 1, 7);
    int xbase = (int)(wg * (31.f/63.f));
    const float* p00 = hp + (d0*32 + h0)*32;
    const float* p01 = hp + (d0*32 + h1)*32;
    const float* p10 = hp + (d1*32 + h0)*32;
    const float* p11 = hp + (d1*32 + h1)*32;
    float V[4];
    #pragma unroll
    for (int c2 = 0; c2 < 4; c2++) {
        int xc = min(xbase + c2, 31);
        float v00 = __ldg(p00 + xc), v01 = __ldg(p01 + xc);
        float v10 = __ldg(p10 + xc), v11 = __ldg(p11 + xc);
        float a = v00 + (v01 - v00)*fh;
        float b2 = v10 + (v11 - v10)*fh;
        V[c2] = a + (b2 - a)*fd;
    }
    float4 ov;
    float* po = (float*)&ov;
    #pragma unroll
    for (int i = 0; i < 4; i++) {
        float pw = (wg + i) * (31.f/63.f);
        int x0 = (int)pw; float fx = pw - (float)x0;
        int k = x0 - xbase;
        float va = (k == 0) ? V[0] : ((k == 1) ? V[1] : V[2]);
        float vb = (k == 0) ? V[1] : ((k == 1) ? V[2] : V[3]);
        po[i] = va + (vb - va)*fx;
    }
    *(float4*)(g_hfup + (size_t)slab*PX + ((d << 6) + h)*64 + wg) = ov;
}

// ------------- K4: 3x3x3 conv, f32x2, 4 outputs/thread, 8 groups of 16 -----
// block (16,8,2): output tile w=64 (4/thread), h=8, d=2
// tile 4 x 10 x 68 (padded for 16B alignment), double buffered.
#define TROW 68
#define TPLANE 680
#define TSIZE 2720
__global__ void k_conv3(const float* __restrict__ x,
                        const float* __restrict__ wflow) {
    __shared__ __align__(16) float tile[2][TSIZE];
    __shared__ __align__(16) float wsm[16*180];
    int bz = blockIdx.z;
    int n = bz >> 3, g = bz & 7;
    int d0 = blockIdx.y * 2;
    int h0 = blockIdx.x * 8;
    int tx = threadIdx.x, ty = threadIdx.y, tz = threadIdx.z;
    int tid = (tz*8 + ty)*16 + tx;            // 0..255

    const float* inb = (g < 4) ? (x + (size_t)(n*64 + g*16)*PX)
                               : (g_hfup + (size_t)(n*64 + (g-4)*16)*PX);
    // stage weights (dup-pair layout: [ch][row(kd*3+kh)][20], pair j=(kw*3+o) at 2j)
    if (g < 4) {
        const float* src = g_w1 + (size_t)(n*64 + g*16)*180;
        for (int idx = tid; idx < 16*180; idx += 256) wsm[idx] = src[idx];
    } else {
        int cbase = (g - 4)*16;
        for (int idx = tid; idx < 16*81; idx += 256) {
            int ch = idx / 81; int r = idx % 81; int tap = r / 3; int o = r % 3;
            int kd = tap/9, kh = (tap/3)%3, kw = tap%3;
            float v = wflow[o*(128*27) + (cbase + ch)*27 + tap];
            int dst = ch*180 + (kd*3 + kh)*20 + 2*(kw*3 + o);
            wsm[dst] = v; wsm[dst + 1] = v;
        }
    }

    // tile fill slots: 11 per thread; off<0 means out-of-range (zero fill)
    int offe[11];
    #pragma unroll
    for (int k = 0; k < 11; k++) {
        int e = tid + k*256;
        int zz = e / TPLANE; int rr = e - zz*TPLANE;
        int yy = rr / TROW;  int xx = rr - yy*TROW;
        int gz = d0 - 1 + zz, gy = h0 - 1 + yy, gx = xx - 1;
        bool ok = (e < TSIZE) && ((unsigned)gz < 16u) && ((unsigned)gy < 64u)
                              && ((unsigned)gx < 64u);
        offe[k] = ok ? ((gz*64 + gy)*64 + gx) : -1;
    }
    bool live10 = (tid + 10*256) < TSIZE;

    unsigned long long accL0 = 0, accL1 = 0, accL2 = 0;
    unsigned long long accR0 = 0, accR1 = 0, accR2 = 0;
    float r[11];
    #pragma unroll
    for (int k = 0; k < 11; k++) r[k] = (offe[k] >= 0) ? __ldg(inb + offe[k]) : 0.f;
    {
        float* b0 = tile[0];
        #pragma unroll
        for (int k = 0; k < 10; k++) b0[tid + k*256] = r[k];
        if (live10) b0[tid + 10*256] = r[10];
    }
    __syncthreads();

    const int tb_off = tz*TPLANE + ty*TROW + 4*tx;
    for (int c = 0; c < 16; c++) {
        const float* tb = tile[c & 1];
        if (c < 15) {
            const float* cb = inb + (size_t)(c + 1)*PX;
            #pragma unroll
            for (int k = 0; k < 11; k++) r[k] = (offe[k] >= 0) ? __ldg(cb + offe[k]) : 0.f;
        }
        const float* wp = wsm + c*180;
        #pragma unroll
        for (int kd = 0; kd < 3; kd++) {
            #pragma unroll
            for (int kh = 0; kh < 3; kh++) {
                const float* rowp = tb + tb_off + kd*TPLANE + kh*TROW;
                F4U A, B;
                A.f = *(const float4*)rowp;
                B.f = *(const float4*)(rowp + 4);
                unsigned long long P12, P34;
                asm("mov.b64 %0, {%1, %2};" : "=l"(P12) : "f"(A.f.y), "f"(A.f.z));
                asm("mov.b64 %0, {%1, %2};" : "=l"(P34) : "f"(A.f.w), "f"(B.f.x));
                unsigned long long P01 = A.u[0], P23 = A.u[1], P45 = B.u[0];
                const float* wr = wp + (kd*3 + kh)*20;
                F4U wA, wB, wC, wD; F2U wE;
                wA.f = *(const float4*)(wr);        // j0, j1
                wB.f = *(const float4*)(wr + 4);    // j2, j3
                wC.f = *(const float4*)(wr + 8);    // j4, j5
                wD.f = *(const float4*)(wr + 12);   // j6, j7
                wE.f = *(const float2*)(wr + 16);   // j8
                // accL (w, w+1): kw0->P01, kw1->P12, kw2->P23
                FMA2(accL0, P01, wA.u[0]);  // j0 = kw0,o0
                FMA2(accL1, P01, wA.u[1]);  // j1 = kw0,o1
                FMA2(accL2, P01, wB.u[0]);  // j2 = kw0,o2
                FMA2(accL0, P12, wB.u[1]);  // j3 = kw1,o0
                FMA2(accL1, P12, wC.u[0]);  // j4
                FMA2(accL2, P12, wC.u[1]);  // j5
                FMA2(accL0, P23, wD.u[0]);  // j6 = kw2,o0
                FMA2(accL1, P23, wD.u[1]);  // j7
                FMA2(accL2, P23, wE.u);     // j8
                // accR (w+2, w+3): kw0->P23, kw1->P34, kw2->P45
                FMA2(accR0, P23, wA.u[0]);
                FMA2(accR1, P23, wA.u[1]);
                FMA2(accR2, P23, wB.u[0]);
                FMA2(accR0, P34, wB.u[1]);
                FMA2(accR1, P34, wC.u[0]);
                FMA2(accR2, P34, wC.u[1]);
                FMA2(accR0, P45, wD.u[0]);
                FMA2(accR1, P45, wD.u[1]);
                FMA2(accR2, P45, wE.u);
            }
        }
        if (c < 15) {
            float* nb2 = tile[(c + 1) & 1];
            #pragma unroll
            for (int k = 0; k < 10; k++) nb2[tid + k*256] = r[k];
            if (live10) nb2[tid + 10*256] = r[10];
        }
        __syncthreads();
    }

    size_t po = ((size_t)(d0 + tz)*64 + (h0 + ty))*64 + 4*tx;
    float* fp = g_flowp[g] + (size_t)n*3*PX + po;
    F2U l0, l1, l2, r0, r1, r2;
    l0.u = accL0; l1.u = accL1; l2.u = accL2;
    r0.u = accR0; r1.u = accR1; r2.u = accR2;
    *(float4*)(fp)        = make_float4(l0.f.x, l0.f.y, r0.f.x, r0.f.y);
    *(float4*)(fp + PX)   = make_float4(l1.f.x, l1.f.y, r1.f.x, r1.f.y);
    *(float4*)(fp + 2*PX) = make_float4(l2.f.x, l2.f.y, r2.f.x, r2.f.y);
}

// -------- K5: flow warp + grid sample, channel-vectorized via yT ------------
// 4 threads per output voxel, each handles 32 channels (float4 loads, FMA2).
__global__ void k_sample(float* __restrict__ out) {
    int tid = threadIdx.x;                    // 256
    int q  = tid >> 2;                        // voxel within block (0..63)
    int cg = tid & 3;                         // channel group (32 ch)
    int p = blockIdx.x*64 + q;                // 0..65535
    int n = blockIdx.y;
    int w = p & 63, h = (p >> 6) & 63, d = p >> 12;

    size_t fo = (size_t)n*3*PX + p;
    float f0 = g_flowp[cg][fo]        + g_flowp[cg+4][fo];
    float f1 = g_flowp[cg][fo + PX]   + g_flowp[cg+4][fo + PX];
    float f2 = g_flowp[cg][fo + 2*PX] + g_flowp[cg+4][fo + 2*PX];
    f0 += __shfl_xor_sync(0xffffffffu, f0, 1);
    f0 += __shfl_xor_sync(0xffffffffu, f0, 2);
    f1 += __shfl_xor_sync(0xffffffffu, f1, 1);
    f1 += __shfl_xor_sync(0xffffffffu, f1, 2);
    f2 += __shfl_xor_sync(0xffffffffu, f2, 1);
    f2 += __shfl_xor_sync(0xffffffffu, f2, 2);

    float gx = (w + f0) * (1.f/64.f);
    float gy = (h + f1) * (1.f/64.f);
    float gz = (d + f2) * (1.f/16.f);
    float ix = ((gx + 1.f)*32.f - 1.f)*0.5f;
    float iy = ((gy + 1.f)*32.f - 1.f)*0.5f;
    float iz = ((gz + 1.f)*8.f  - 1.f)*0.5f;
    float fx0 = floorf(ix), fy0 = floorf(iy), fz0 = floorf(iz);
    int x0 = (int)fx0, y0 = (int)fy0, z0 = (int)fz0;
    float fx = ix - fx0, fy = iy - fy0, fz = iz - fz0;
    float wx0 = 1.f - fx, wy0 = 1.f - fy, wz0 = 1.f - fz;

    int x0c = min(max(x0, 0), 31), x1c = min(max(x0 + 1, 0), 31);
    int y0c = min(max(y0, 0), 31), y1c = min(max(y0 + 1, 0), 31);
    int z0c = min(max(z0, 0), 7),  z1c = min(max(z0 + 1, 0), 7);
    bool vx0 = ((unsigned)x0 < 32u), vx1 = ((unsigned)(x0 + 1) < 32u);
    bool vy0 = ((unsigned)y0 < 32u), vy1 = ((unsigned)(y0 + 1) < 32u);
    bool vz0 = ((unsigned)z0 < 8u),  vz1 = ((unsigned)(z0 + 1) < 8u);

    int o[8];
    o[0] = (z0c*32 + y0c)*32 + x0c;
    o[1] = (z0c*32 + y0c)*32 + x1c;
    o[2] = (z0c*32 + y1c)*32 + x0c;
    o[3] = (z0c*32 + y1c)*32 + x1c;
    o[4] = (z1c*32 + y0c)*32 + x0c;
    o[5] = (z1c*32 + y0c)*32 + x1c;
    o[6] = (z1c*32 + y1c)*32 + x0c;
    o[7] = (z1c*32 + y1c)*32 + x1c;
    float t[8];
    t[0] = (vz0 && vy0 && vx0) ? wz0*wy0*wx0 : 0.f;
    t[1] = (vz0 && vy0 && vx1) ? wz0*wy0*fx  : 0.f;
    t[2] = (vz0 && vy1 && vx0) ? wz0*fy*wx0  : 0.f;
    t[3] = (vz0 && vy1 && vx1) ? wz0*fy*fx   : 0.f;
    t[4] = (vz1 && vy0 && vx0) ? fz*wy0*wx0  : 0.f;
    t[5] = (vz1 && vy0 && vx1) ? fz*wy0*fx   : 0.f;
    t[6] = (vz1 && vy1 && vx0) ? fz*fy*wx0   : 0.f;
    t[7] = (vz1 && vy1 && vx1) ? fz*fy*fx    : 0.f;

    const float* ytb = g_yT + ((size_t)n*PY)*CYC + cg*32;
    unsigned long long acc[16];
    #pragma unroll
    for (int j = 0; j < 16; j++) acc[j] = 0ULL;
    #pragma unroll
    for (int i = 0; i < 8; i++) {
        const float4* tp = (const float4*)(ytb + (size_t)o[i]*CYC);
        F2U tw; tw.f = make_float2(t[i], t[i]);
        #pragma unroll
        for (int j = 0; j < 8; j++) {
            F4U v; v.f = __ldg(tp + j);
            FMA2(acc[2*j],     v.u[0], tw.u);
            FMA2(acc[2*j + 1], v.u[1], tw.u);
        }
    }
    float* ob = out + (size_t)n*CYC*PX + (size_t)(cg*32)*PX + p;
    #pragma unroll
    for (int j = 0; j < 8; j++) {
        F2U a, b2; a.u = acc[2*j]; b2.u = acc[2*j + 1];
        ob[(size_t)(4*j + 0)*PX] = a.f.x;
        ob[(size_t)(4*j + 1)*PX] = a.f.y;
        ob[(size_t)(4*j + 2)*PX] = b2.f.x;
        ob[(size_t)(4*j + 3)*PX] = b2.f.y;
    }
}

// --------------------------------- launch ----------------------------------
extern "C" void kernel_launch(void* const* d_in, const int* in_sizes, int n_in,
                              void* d_out, int out_size) {
    const float* x     = (const float*)d_in[0];
    const float* y     = (const float*)d_in[1];
    const float* wdh   = (const float*)d_in[2];
    const float* wdl   = (const float*)d_in[3];
    const float* wflow = (const float*)d_in[4];
    const float* wa    = (const float*)d_in[5];
    const float* wc    = (const float*)d_in[6];
    float* out = (float*)d_out;

    k_pre<<<2432, 256>>>(y, wdh, x);
    k_prep<<<NB, 256>>>(wdl, wa, wc, wflow);
    k_up<<<(NB*CO*PX/4)/256, 256>>>();
    k_conv3<<<dim3(8, 8, NB*8), dim3(16, 8, 2)>>>(x, wflow);
    k_sample<<<dim3(PX/64, NB), 256>>>(out);
}

// round 5
// speedup vs baseline: 2.2018x; 1.0250x over previous
#include <cuda_runtime.h>
#include <math.h>

#define NB 2
#define CXC 64
#define CYC 128
#define CO  64
#define DD  16
#define HH  64
#define WW  64
#define PX  (DD*HH*WW)    /* 65536 */
#define PY  (8*32*32)     /* 8192  */

// packed f32x2 FMA (Blackwell): one instr = 2 fp32 FMA
#define FMA2(acc, a, b) asm("fma.rn.f32x2 %0, %1, %2, %0;" : "+l"(acc) : "l"(a), "l"(b))

union F2U { float2 f; unsigned long long u; };
union F4U { float4 f; unsigned long long u[2]; };

// ---------------- scratch (device globals; no allocation) ----------------
__device__ float g_xmean[NB*CXC];
__device__ float g_w1[NB*64*108];                // folded x-path weights [n][i][row][12]
__device__ float g_hf[NB*CO*PY];                 // 4 MB
__device__ float g_hfup[(size_t)NB*CO*PX];       // 33 MB
__device__ float g_flowp[8][NB*3*PX];            // partial flows per channel-group
__device__ float g_yT[(size_t)NB*PY*CYC];        // 8 MB  y transposed to [n][p][c]

// ===== K1 (fused): hf 1x1 conv  |  xmean  |  y transpose ====================
__global__ void k_pre(const float* __restrict__ y,
                      const float* __restrict__ wdh,
                      const float* __restrict__ x) {
    __shared__ float sh[2112];
    int b = blockIdx.x;
    int tid = threadIdx.x;                       // 256

    if (b < 256) {
        // ---- hf: g_hf[n][og*16+o][p] = sum_i wdh[og*16+o][i] * y[n][i][p]
        int n  = b >> 7;
        int r  = b & 127;
        int og = r >> 5;
        int pb = r & 31;
        float (*wT)[16] = (float(*)[16])sh;      // wT[i][o_local]
        for (int idx = tid; idx < 128*16; idx += 256) {
            int ol = idx >> 7, i = idx & 127;
            wT[i][ol] = wdh[(og*16 + ol)*128 + i];
        }
        __syncthreads();
        int p = pb*256 + tid;
        const float* yp = y + (size_t)n*CYC*PY + p;
        float acc[16];
        #pragma unroll
        for (int o = 0; o < 16; o++) acc[o] = 0.f;
        for (int i = 0; i < 128; i++) {
            float v = yp[(size_t)i*PY];
            #pragma unroll
            for (int o4 = 0; o4 < 4; o4++) {
                float4 w4 = *(const float4*)&wT[i][o4*4];
                acc[o4*4+0] = fmaf(w4.x, v, acc[o4*4+0]);
                acc[o4*4+1] = fmaf(w4.y, v, acc[o4*4+1]);
                acc[o4*4+2] = fmaf(w4.z, v, acc[o4*4+2]);
                acc[o4*4+3] = fmaf(w4.w, v, acc[o4*4+3]);
            }
        }
        float* op = g_hf + (size_t)(n*CO + og*16)*PY + p;
        #pragma unroll
        for (int o = 0; o < 16; o++) op[(size_t)o*PY] = acc[o];
    } else if (b < 384) {
        // ---- xmean over x[nc][:]
        int nc = b - 256;
        const float4* p4 = (const float4*)(x + (size_t)nc * PX);
        float s = 0.f;
        #pragma unroll 4
        for (int i = tid; i < PX/4; i += 256) {
            float4 v = p4[i];
            s += (v.x + v.y) + (v.z + v.w);
        }
        #pragma unroll
        for (int o = 16; o > 0; o >>= 1) s += __shfl_xor_sync(0xffffffffu, s, o);
        if ((tid & 31) == 0) sh[tid >> 5] = s;
        __syncthreads();
        if (tid < 8) {
            float t = sh[tid];
            #pragma unroll
            for (int o = 4; o > 0; o >>= 1) t += __shfl_xor_sync(0xffu, t, o, 8);
            if (tid == 0) g_xmean[nc] = t * (1.f / PX);
        }
    } else {
        // ---- transpose y[n][c][pp] -> g_yT[n][pp][c], 32x32 tiles
        int bb = b - 384;                        // 0..2047
        int n  = bb >> 10;
        int r  = bb & 1023;
        int pt = r >> 2;                         // 0..255
        int ct = r & 3;                          // 0..3
        int tx = tid & 31, ty = tid >> 5;        // ty 0..7
        const float* yb = y + (size_t)n*CYC*PY;
        #pragma unroll
        for (int k = 0; k < 4; k++) {
            int cl = ty + k*8;
            sh[cl*33 + tx] = yb[(size_t)(ct*32 + cl)*PY + pt*32 + tx];
        }
        __syncthreads();
        float* ob = g_yT + ((size_t)n*PY)*CYC;
        #pragma unroll
        for (int k = 0; k < 4; k++) {
            int pl = ty + k*8;
            ob[(size_t)(pt*32 + pl)*CYC + ct*32 + tx] = sh[tx*33 + pl];
        }
    }
}

// ---- K2: fold SE attention + 1x1 conv + flow-conv low half into W1_n ----
__global__ void k_prep(const float* __restrict__ wdl,
                       const float* __restrict__ wa,
                       const float* __restrict__ wc,
                       const float* __restrict__ wflow) {
    int n = blockIdx.x, t = threadIdx.x;     // 256 threads
    __shared__ float xm[64], pooled[64], scale[64];
    __shared__ float M[64][64];
    if (t < 64) xm[t] = g_xmean[n*64 + t];
    __syncthreads();
    if (t < 64) {
        float s = 0.f;
        for (int i = 0; i < 64; i++) s += wdl[t*64 + i] * xm[i];
        pooled[t] = s;
    }
    __syncthreads();
    if (t < 64) {
        float a = 0.f;
        for (int i = 0; i < 64; i++) a += wa[t*64 + i] * pooled[i];
        scale[t] = 1.f + 1.f / (1.f + expf(-a));
    }
    __syncthreads();
    for (int idx = t; idx < 4096; idx += 256) {
        int o = idx >> 6, i = idx & 63;
        float acc = 0.f;
        for (int c = 0; c < 64; c++) acc += wc[o*64 + c] * scale[c] * wdl[c*64 + i];
        M[o][i] = acc;
    }
    __syncthreads();
    for (int idx = t; idx < 64*81; idx += 256) {
        int i = idx / 81; int r = idx % 81; int tap = r / 3; int o3 = r % 3;
        float acc = 0.f;
        for (int c = 0; c < 64; c++)
            acc += wflow[o3*(128*27) + (64 + c)*27 + tap] * M[c][i];
        int kd = tap/9, kh = (tap/3)%3, kw = tap%3;
        g_w1[(size_t)(n*64 + i)*108 + (kd*3 + kh)*12 + (kw*3 + o3)] = acc;
    }
}

// ------ K3: trilinear upsample, 4 outputs/thread, shared source columns ----
__global__ void k_up() {
    int t = blockIdx.x*256 + threadIdx.x;    // over NB*CO*16*64*16
    int wg = (t & 15) << 2;                  // w start: 0,4,...,60
    int h  = (t >> 4) & 63;
    int d  = (t >> 10) & 15;
    int slab = t >> 14;                      // n*CO + c
    const float* hp = g_hf + (size_t)slab * PY;
    float ph = h * (31.f/63.f);
    float pd = d * (7.f/15.f);
    int h0 = (int)ph; float fh = ph - (float)h0; int h1 = min(h0 + 1, 31);
    int d0 = (int)pd; float fd = pd - (float)d0; int d1 = min(d0 + 1, 7);
    int xbase = (int)(wg * (31.f/63.f));
    const float* p00 = hp + (d0*32 + h0)*32;
    const float* p01 = hp + (d0*32 + h1)*32;
    const float* p10 = hp + (d1*32 + h0)*32;
    const float* p11 = hp + (d1*32 + h1)*32;
    float V[4];
    #pragma unroll
    for (int c2 = 0; c2 < 4; c2++) {
        int xc = min(xbase + c2, 31);
        float v00 = __ldg(p00 + xc), v01 = __ldg(p01 + xc);
        float v10 = __ldg(p10 + xc), v11 = __ldg(p11 + xc);
        float a = v00 + (v01 - v00)*fh;
        float b2 = v10 + (v11 - v10)*fh;
        V[c2] = a + (b2 - a)*fd;
    }
    float4 ov;
    float* po = (float*)&ov;
    #pragma unroll
    for (int i = 0; i < 4; i++) {
        float pw = (wg + i) * (31.f/63.f);
        int x0 = (int)pw; float fx = pw - (float)x0;
        int k = x0 - xbase;
        float va = (k == 0) ? V[0] : ((k == 1) ? V[1] : V[2]);
        float vb = (k == 0) ? V[1] : ((k == 1) ? V[2] : V[3]);
        po[i] = va + (vb - va)*fx;
    }
    *(float4*)(g_hfup + (size_t)slab*PX + ((d << 6) + h)*64 + wg) = ov;
}

// ------------- K4: 3x3x3 conv, f32x2, 8 outputs/thread, cp.async fill ------
// block 256 = (tx 8, ty 16, tz 2): tile w=64(+halo), h=16, d=2
// smem tile 4 x 18 x 72 (idx = gx+4; idx 3 and 68 are permanent zeros).
#define TROW 72
#define TYD  18
#define TZD  4
#define TSIZE (TZD*TYD*TROW)   /* 5184 */
__global__ void k_conv3(const float* __restrict__ x,
                        const float* __restrict__ wflow) {
    __shared__ __align__(16) float tile[2][TSIZE];
    __shared__ __align__(16) float wsm[16*108];
    int bz = blockIdx.z;
    int n = bz >> 3, g = bz & 7;
    int d0 = blockIdx.y * 2;
    int h0 = blockIdx.x * 16;
    int tid = threadIdx.x;
    int tx = tid & 7, ty = (tid >> 3) & 15, tz = tid >> 7;

    const float* inb = (g < 4) ? (x + (size_t)(n*64 + g*16)*PX)
                               : (g_hfup + (size_t)(n*64 + (g-4)*16)*PX);
    // stage weights: scalar layout [ch][row(kd*3+kh)][12] (slots 0..8 used)
    if (g < 4) {
        const float* src = g_w1 + (size_t)(n*64 + g*16)*108;
        for (int idx = tid; idx < 16*108; idx += 256) wsm[idx] = src[idx];
    } else {
        int cbase = (g - 4)*16;
        for (int idx = tid; idx < 16*81; idx += 256) {
            int ch = idx / 81; int r = idx % 81; int tap = r / 3; int o = r % 3;
            int kd = tap/9, kh = (tap/3)%3, kw = tap%3;
            wsm[ch*108 + (kd*3 + kh)*12 + kw*3 + o] =
                wflow[o*(128*27) + (cbase + ch)*27 + tap];
        }
    }
    // permanent zero halos at idx 3 (gx=-1) and 68 (gx=64), both buffers
    for (int idx = tid; idx < TZD*TYD*2*2; idx += 256) {
        int b2 = idx & 1; int r2 = idx >> 1; int side = r2 & 1; int row = r2 >> 1;
        tile[b2][row*TROW + (side ? 68 : 3)] = 0.f;
    }

    // fill-slot precompute: slot k covers 16B chunk (tid&15) of row (tid>>4)+16k
    int goff[5];
    {
        int x16 = (tid & 15) * 4;
        #pragma unroll
        for (int k = 0; k < 5; k++) {
            int row = (tid >> 4) + 16*k;
            int zz = row / TYD, yy = row - zz*TYD;
            int gz = d0 - 1 + zz, gy = h0 - 1 + yy;
            bool ok = (row < TZD*TYD) && ((unsigned)gz < 16u) && ((unsigned)gy < 64u);
            goff[k] = ok ? ((gz*64 + gy)*64 + x16) : -1;
        }
    }
    bool live4 = (tid + 1024) < (TZD*TYD*16);
    unsigned dstbase =
        (unsigned)__cvta_generic_to_shared(&tile[0][0])
        + (unsigned)(((tid >> 4)*TROW + 4 + (tid & 15)*4) * 4);

#define FILL(BSEL, CPTR) do {                                                  \
    unsigned _db = dstbase + (unsigned)((BSEL)*(TSIZE*4));                     \
    _Pragma("unroll")                                                          \
    for (int _k = 0; _k < 5; _k++) {                                           \
        if (_k < 4 || live4) {                                                 \
            int _go = goff[_k];                                                \
            int _sz = (_go < 0) ? 0 : 16;                                      \
            const float* _sp = (CPTR) + ((_go < 0) ? 0 : _go);                 \
            asm volatile("cp.async.ca.shared.global [%0], [%1], 16, %2;"       \
                :: "r"(_db + (unsigned)(_k*(16*TROW*4))), "l"(_sp), "r"(_sz)); \
        }                                                                      \
    }                                                                          \
    asm volatile("cp.async.commit_group;" ::: "memory");                      \
} while (0)

    const float* cptr = inb;
    FILL(0, cptr);

    unsigned long long acc[12];
    #pragma unroll
    for (int j = 0; j < 12; j++) acc[j] = 0ULL;

    for (int c = 0; c < 16; c++) {
        if (c < 15) {
            FILL((c + 1) & 1, cptr + PX);
            asm volatile("cp.async.wait_group 1;" ::: "memory");
        } else {
            asm volatile("cp.async.wait_group 0;" ::: "memory");
        }
        __syncthreads();
        const float* tb = tile[c & 1];
        const float* wch = wsm + c*108;
        #pragma unroll
        for (int kd = 0; kd < 3; kd++) {
            #pragma unroll
            for (int kh = 0; kh < 3; kh++) {
                const float* rowp = tb + ((tz + kd)*TYD + (ty + kh))*TROW + 8*tx;
                F4U A, B, C, D;
                A.f = *(const float4*)rowp;          // f0..3  (x = 8tx-4 .. )
                B.f = *(const float4*)(rowp + 4);    // f4..7
                C.f = *(const float4*)(rowp + 8);    // f8..11
                D.f = *(const float4*)(rowp + 12);   // f12..15
                unsigned long long O0, O1, O2, O3, O4;
                asm("mov.b64 %0, {%1,%2};" : "=l"(O0) : "f"(A.f.w), "f"(B.f.x)); // f3f4
                asm("mov.b64 %0, {%1,%2};" : "=l"(O1) : "f"(B.f.y), "f"(B.f.z)); // f5f6
                asm("mov.b64 %0, {%1,%2};" : "=l"(O2) : "f"(B.f.w), "f"(C.f.x)); // f7f8
                asm("mov.b64 %0, {%1,%2};" : "=l"(O3) : "f"(C.f.y), "f"(C.f.z)); // f9f10
                asm("mov.b64 %0, {%1,%2};" : "=l"(O4) : "f"(C.f.w), "f"(D.f.x)); // f11f12
                unsigned long long E0 = B.u[0], E1 = B.u[1], E2 = C.u[0], E3 = C.u[1];
                const float* wr = wch + (kd*3 + kh)*12;
                F4U W0, W1, W2;
                W0.f = *(const float4*)wr;
                W1.f = *(const float4*)(wr + 4);
                W2.f = *(const float4*)(wr + 8);
                unsigned long long WP[9];
                asm("mov.b64 %0, {%1,%1};" : "=l"(WP[0]) : "f"(W0.f.x));
                asm("mov.b64 %0, {%1,%1};" : "=l"(WP[1]) : "f"(W0.f.y));
                asm("mov.b64 %0, {%1,%1};" : "=l"(WP[2]) : "f"(W0.f.z));
                asm("mov.b64 %0, {%1,%1};" : "=l"(WP[3]) : "f"(W0.f.w));
                asm("mov.b64 %0, {%1,%1};" : "=l"(WP[4]) : "f"(W1.f.x));
                asm("mov.b64 %0, {%1,%1};" : "=l"(WP[5]) : "f"(W1.f.y));
                asm("mov.b64 %0, {%1,%1};" : "=l"(WP[6]) : "f"(W1.f.z));
                asm("mov.b64 %0, {%1,%1};" : "=l"(WP[7]) : "f"(W1.f.w));
                asm("mov.b64 %0, {%1,%1};" : "=l"(WP[8]) : "f"(W2.f.x));
                #pragma unroll
                for (int o = 0; o < 3; o++) {
                    FMA2(acc[0 + o], O0, WP[o]);        // kw=0
                    FMA2(acc[3 + o], O1, WP[o]);
                    FMA2(acc[6 + o], O2, WP[o]);
                    FMA2(acc[9 + o], O3, WP[o]);
                    FMA2(acc[0 + o], E0, WP[3 + o]);    // kw=1
                    FMA2(acc[3 + o], E1, WP[3 + o]);
                    FMA2(acc[6 + o], E2, WP[3 + o]);
                    FMA2(acc[9 + o], E3, WP[3 + o]);
                    FMA2(acc[0 + o], O1, WP[6 + o]);    // kw=2
                    FMA2(acc[3 + o], O2, WP[6 + o]);
                    FMA2(acc[6 + o], O3, WP[6 + o]);
                    FMA2(acc[9 + o], O4, WP[6 + o]);
                }
            }
        }
        __syncthreads();
        cptr += PX;
    }
#undef FILL

    size_t po = ((size_t)(d0 + tz)*64 + (h0 + ty))*64 + 8*tx;
    float* fp = g_flowp[g] + (size_t)n*3*PX + po;
    #pragma unroll
    for (int o = 0; o < 3; o++) {
        F2U a0, a1, a2, a3;
        a0.u = acc[0 + o]; a1.u = acc[3 + o]; a2.u = acc[6 + o]; a3.u = acc[9 + o];
        *(float4*)(fp + (size_t)o*PX)     = make_float4(a0.f.x, a0.f.y, a1.f.x, a1.f.y);
        *(float4*)(fp + (size_t)o*PX + 4) = make_float4(a2.f.x, a2.f.y, a3.f.x, a3.f.y);
    }
}

// -------- K5: flow warp + grid sample, channel-vectorized via yT ------------
__global__ void k_sample(float* __restrict__ out) {
    int tid = threadIdx.x;                    // 256
    int q  = tid >> 2;                        // voxel within block (0..63)
    int cg = tid & 3;                         // channel group (32 ch)
    int p = blockIdx.x*64 + q;                // 0..65535
    int n = blockIdx.y;
    int w = p & 63, h = (p >> 6) & 63, d = p >> 12;

    size_t fo = (size_t)n*3*PX + p;
    float f0 = g_flowp[cg][fo]        + g_flowp[cg+4][fo];
    float f1 = g_flowp[cg][fo + PX]   + g_flowp[cg+4][fo + PX];
    float f2 = g_flowp[cg][fo + 2*PX] + g_flowp[cg+4][fo + 2*PX];
    f0 += __shfl_xor_sync(0xffffffffu, f0, 1);
    f0 += __shfl_xor_sync(0xffffffffu, f0, 2);
    f1 += __shfl_xor_sync(0xffffffffu, f1, 1);
    f1 += __shfl_xor_sync(0xffffffffu, f1, 2);
    f2 += __shfl_xor_sync(0xffffffffu, f2, 1);
    f2 += __shfl_xor_sync(0xffffffffu, f2, 2);

    float gx = (w + f0) * (1.f/64.f);
    float gy = (h + f1) * (1.f/64.f);
    float gz = (d + f2) * (1.f/16.f);
    float ix = ((gx + 1.f)*32.f - 1.f)*0.5f;
    float iy = ((gy + 1.f)*32.f - 1.f)*0.5f;
    float iz = ((gz + 1.f)*8.f  - 1.f)*0.5f;
    float fx0 = floorf(ix), fy0 = floorf(iy), fz0 = floorf(iz);
    int x0 = (int)fx0, y0 = (int)fy0, z0 = (int)fz0;
    float fx = ix - fx0, fy = iy - fy0, fz = iz - fz0;
    float wx0 = 1.f - fx, wy0 = 1.f - fy, wz0 = 1.f - fz;

    int x0c = min(max(x0, 0), 31), x1c = min(max(x0 + 1, 0), 31);
    int y0c = min(max(y0, 0), 31), y1c = min(max(y0 + 1, 0), 31);
    int z0c = min(max(z0, 0), 7),  z1c = min(max(z0 + 1, 0), 7);
    bool vx0 = ((unsigned)x0 < 32u), vx1 = ((unsigned)(x0 + 1) < 32u);
    bool vy0 = ((unsigned)y0 < 32u), vy1 = ((unsigned)(y0 + 1) < 32u);
    bool vz0 = ((unsigned)z0 < 8u),  vz1 = ((unsigned)(z0 + 1) < 8u);

    int o[8];
    o[0] = (z0c*32 + y0c)*32 + x0c;
    o[1] = (z0c*32 + y0c)*32 + x1c;
    o[2] = (z0c*32 + y1c)*32 + x0c;
    o[3] = (z0c*32 + y1c)*32 + x1c;
    o[4] = (z1c*32 + y0c)*32 + x0c;
    o[5] = (z1c*32 + y0c)*32 + x1c;
    o[6] = (z1c*32 + y1c)*32 + x0c;
    o[7] = (z1c*32 + y1c)*32 + x1c;
    float t[8];
    t[0] = (vz0 && vy0 && vx0) ? wz0*wy0*wx0 : 0.f;
    t[1] = (vz0 && vy0 && vx1) ? wz0*wy0*fx  : 0.f;
    t[2] = (vz0 && vy1 && vx0) ? wz0*fy*wx0  : 0.f;
    t[3] = (vz0 && vy1 && vx1) ? wz0*fy*fx   : 0.f;
    t[4] = (vz1 && vy0 && vx0) ? fz*wy0*wx0  : 0.f;
    t[5] = (vz1 && vy0 && vx1) ? fz*wy0*fx   : 0.f;
    t[6] = (vz1 && vy1 && vx0) ? fz*fy*wx0   : 0.f;
    t[7] = (vz1 && vy1 && vx1) ? fz*fy*fx    : 0.f;

    const float* ytb = g_yT + ((size_t)n*PY)*CYC + cg*32;
    unsigned long long acc[16];
    #pragma unroll
    for (int j = 0; j < 16; j++) acc[j] = 0ULL;
    #pragma unroll
    for (int i = 0; i < 8; i++) {
        const float4* tp = (const float4*)(ytb + (size_t)o[i]*CYC);
        F2U tw; tw.f = make_float2(t[i], t[i]);
        #pragma unroll
        for (int j = 0; j < 8; j++) {
            F4U v; v.f = __ldg(tp + j);
            FMA2(acc[2*j],     v.u[0], tw.u);
            FMA2(acc[2*j + 1], v.u[1], tw.u);
        }
    }
    float* ob = out + (size_t)n*CYC*PX + (size_t)(cg*32)*PX + p;
    #pragma unroll
    for (int j = 0; j < 8; j++) {
        F2U a, b2; a.u = acc[2*j]; b2.u = acc[2*j + 1];
        ob[(size_t)(4*j + 0)*PX] = a.f.x;
        ob[(size_t)(4*j + 1)*PX] = a.f.y;
        ob[(size_t)(4*j + 2)*PX] = b2.f.x;
        ob[(size_t)(4*j + 3)*PX] = b2.f.y;
    }
}

// --------------------------------- launch ----------------------------------
extern "C" void kernel_launch(void* const* d_in, const int* in_sizes, int n_in,
                              void* d_out, int out_size) {
    const float* x     = (const float*)d_in[0];
    const float* y     = (const float*)d_in[1];
    const float* wdh   = (const float*)d_in[2];
    const float* wdl   = (const float*)d_in[3];
    const float* wflow = (const float*)d_in[4];
    const float* wa    = (const float*)d_in[5];
    const float* wc    = (const float*)d_in[6];
    float* out = (float*)d_out;

    k_pre<<<2432, 256>>>(y, wdh, x);
    k_prep<<<NB, 256>>>(wdl, wa, wc, wflow);
    k_up<<<(NB*CO*PX/4)/256, 256>>>();
    k_conv3<<<dim3(4, 8, NB*8), 256>>>(x, wflow);
    k_sample<<<dim3(PX/64, NB), 256>>>(out);
}

// round 7
// speedup vs baseline: 3.0997x; 1.4078x over previous
#include <cuda_runtime.h>
#include <math.h>

#define NB 2
#define CXC 64
#define CYC 128
#define CO  64
#define DD  16
#define HH  64
#define WW  64
#define PX  (DD*HH*WW)    /* 65536 */
#define PY  (8*32*32)     /* 8192  */

// packed f32x2 FMA (Blackwell): one instr = 2 fp32 FMA
#define FMA2(acc, a, b) asm("fma.rn.f32x2 %0, %1, %2, %0;" : "+l"(acc) : "l"(a), "l"(b))

union F2U { float2 f; unsigned long long u; };
union F4U { float4 f; unsigned long long u[2]; };

// ---------------- scratch (device globals; no allocation) ----------------
__device__ float g_xmean[NB*CXC];
__device__ float g_w1[NB*64*108];                // folded x-path weights [n][i][row][12]
__device__ float g_hf[NB*CO*PY];                 // 4 MB
__device__ float g_hfup[(size_t)NB*CO*PX];       // 33 MB
__device__ float g_flowp[16][NB*3*PX];           // partial flows per channel-group
__device__ float g_flow[NB*3*PX];                // summed flow
__device__ float g_yT[(size_t)NB*PY*CYC];        // 8 MB  y transposed to [n][p][c]

// ===== K1 (fused): hf 1x1 conv  |  xmean  |  y transpose ====================
__global__ void k_pre(const float* __restrict__ y,
                      const float* __restrict__ wdh,
                      const float* __restrict__ x) {
    __shared__ float sh[2112];
    int b = blockIdx.x;
    int tid = threadIdx.x;                       // 256

    if (b < 256) {
        int n  = b >> 7;
        int r  = b & 127;
        int og = r >> 5;
        int pb = r & 31;
        float (*wT)[16] = (float(*)[16])sh;      // wT[i][o_local]
        for (int idx = tid; idx < 128*16; idx += 256) {
            int ol = idx >> 7, i = idx & 127;
            wT[i][ol] = wdh[(og*16 + ol)*128 + i];
        }
        __syncthreads();
        int p = pb*256 + tid;
        const float* yp = y + (size_t)n*CYC*PY + p;
        float acc[16];
        #pragma unroll
        for (int o = 0; o < 16; o++) acc[o] = 0.f;
        for (int i = 0; i < 128; i++) {
            float v = yp[(size_t)i*PY];
            #pragma unroll
            for (int o4 = 0; o4 < 4; o4++) {
                float4 w4 = *(const float4*)&wT[i][o4*4];
                acc[o4*4+0] = fmaf(w4.x, v, acc[o4*4+0]);
                acc[o4*4+1] = fmaf(w4.y, v, acc[o4*4+1]);
                acc[o4*4+2] = fmaf(w4.z, v, acc[o4*4+2]);
                acc[o4*4+3] = fmaf(w4.w, v, acc[o4*4+3]);
            }
        }
        float* op = g_hf + (size_t)(n*CO + og*16)*PY + p;
        #pragma unroll
        for (int o = 0; o < 16; o++) op[(size_t)o*PY] = acc[o];
    } else if (b < 384) {
        int nc = b - 256;
        const float4* p4 = (const float4*)(x + (size_t)nc * PX);
        float s = 0.f;
        #pragma unroll 4
        for (int i = tid; i < PX/4; i += 256) {
            float4 v = p4[i];
            s += (v.x + v.y) + (v.z + v.w);
        }
        #pragma unroll
        for (int o = 16; o > 0; o >>= 1) s += __shfl_xor_sync(0xffffffffu, s, o);
        if ((tid & 31) == 0) sh[tid >> 5] = s;
        __syncthreads();
        if (tid < 8) {
            float t = sh[tid];
            #pragma unroll
            for (int o = 4; o > 0; o >>= 1) t += __shfl_xor_sync(0xffu, t, o, 8);
            if (tid == 0) g_xmean[nc] = t * (1.f / PX);
        }
    } else {
        int bb = b - 384;                        // 0..2047
        int n  = bb >> 10;
        int r  = bb & 1023;
        int pt = r >> 2;                         // 0..255
        int ct = r & 3;                          // 0..3
        int tx = tid & 31, ty = tid >> 5;        // ty 0..7
        const float* yb = y + (size_t)n*CYC*PY;
        #pragma unroll
        for (int k = 0; k < 4; k++) {
            int cl = ty + k*8;
            sh[cl*33 + tx] = yb[(size_t)(ct*32 + cl)*PY + pt*32 + tx];
        }
        __syncthreads();
        float* ob = g_yT + ((size_t)n*PY)*CYC;
        #pragma unroll
        for (int k = 0; k < 4; k++) {
            int pl = ty + k*8;
            ob[(size_t)(pt*32 + pl)*CYC + ct*32 + tx] = sh[tx*33 + pl];
        }
    }
}

// ---- K2: fold SE attention + 1x1 conv + flow-conv low half into W1_n ----
__global__ void k_prep(const float* __restrict__ wdl,
                       const float* __restrict__ wa,
                       const float* __restrict__ wc,
                       const float* __restrict__ wflow) {
    int n = blockIdx.x, t = threadIdx.x;     // 256 threads
    __shared__ float xm[64], pooled[64], scale[64];
    __shared__ float M[64][64];
    if (t < 64) xm[t] = g_xmean[n*64 + t];
    __syncthreads();
    if (t < 64) {
        float s = 0.f;
        for (int i = 0; i < 64; i++) s += wdl[t*64 + i] * xm[i];
        pooled[t] = s;
    }
    __syncthreads();
    if (t < 64) {
        float a = 0.f;
        for (int i = 0; i < 64; i++) a += wa[t*64 + i] * pooled[i];
        scale[t] = 1.f + 1.f / (1.f + expf(-a));
    }
    __syncthreads();
    for (int idx = t; idx < 4096; idx += 256) {
        int o = idx >> 6, i = idx & 63;
        float acc = 0.f;
        for (int c = 0; c < 64; c++) acc += wc[o*64 + c] * scale[c] * wdl[c*64 + i];
        M[o][i] = acc;
    }
    __syncthreads();
    for (int idx = t; idx < 64*81; idx += 256) {
        int i = idx / 81; int r = idx % 81; int tap = r / 3; int o3 = r % 3;
        float acc = 0.f;
        for (int c = 0; c < 64; c++)
            acc += wflow[o3*(128*27) + (64 + c)*27 + tap] * M[c][i];
        int kd = tap/9, kh = (tap/3)%3, kw = tap%3;
        g_w1[(size_t)(n*64 + i)*108 + (kd*3 + kh)*12 + (kw*3 + o3)] = acc;
    }
}

// ------ K3: trilinear upsample, 4 outputs/thread, shared source columns ----
__global__ void k_up() {
    int t = blockIdx.x*256 + threadIdx.x;    // over NB*CO*16*64*16
    int wg = (t & 15) << 2;                  // w start: 0,4,...,60
    int h  = (t >> 4) & 63;
    int d  = (t >> 10) & 15;
    int slab = t >> 14;                      // n*CO + c
    const float* hp = g_hf + (size_t)slab * PY;
    float ph = h * (31.f/63.f);
    float pd = d * (7.f/15.f);
    int h0 = (int)ph; float fh = ph - (float)h0; int h1 = min(h0 + 1, 31);
    int d0 = (int)pd; float fd = pd - (float)d0; int d1 = min(d0 + 1, 7);
    int xbase = (int)(wg * (31.f/63.f));
    const float* p00 = hp + (d0*32 + h0)*32;
    const float* p01 = hp + (d0*32 + h1)*32;
    const float* p10 = hp + (d1*32 + h0)*32;
    const float* p11 = hp + (d1*32 + h1)*32;
    float V[4];
    #pragma unroll
    for (int c2 = 0; c2 < 4; c2++) {
        int xc = min(xbase + c2, 31);
        float v00 = __ldg(p00 + xc), v01 = __ldg(p01 + xc);
        float v10 = __ldg(p10 + xc), v11 = __ldg(p11 + xc);
        float a = v00 + (v01 - v00)*fh;
        float b2 = v10 + (v11 - v10)*fh;
        V[c2] = a + (b2 - a)*fd;
    }
    float4 ov;
    float* po = (float*)&ov;
    #pragma unroll
    for (int i = 0; i < 4; i++) {
        float pw = (wg + i) * (31.f/63.f);
        int x0 = (int)pw; float fx = pw - (float)x0;
        int k = x0 - xbase;
        float va = (k == 0) ? V[0] : ((k == 1) ? V[1] : V[2]);
        float vb = (k == 0) ? V[1] : ((k == 1) ? V[2] : V[3]);
        po[i] = va + (vb - va)*fx;
    }
    *(float4*)(g_hfup + (size_t)slab*PX + ((d << 6) + h)*64 + wg) = ov;
}

// ------------- K4: 3x3x3 conv, f32x2, dz=2 x w=8 per thread ----------------
// block 128 = (tx 8, ty 16): outputs d0..d0+1, h0..h0+15, w 0..63
// smem tile 4 x 18 x 72 (gx stored at gx+4; idx 3 and 68 permanent zeros).
#define TROW 72
#define TYD  18
#define TZD  4
#define TSIZE (TZD*TYD*TROW)   /* 5184 */
#define GC 8                   /* channels per group */
__global__ void __launch_bounds__(128) k_conv3(const float* __restrict__ x,
                                               const float* __restrict__ wflow) {
    __shared__ __align__(16) float tile[2][TSIZE];
    __shared__ __align__(16) float wsm[GC*108];
    __shared__ int rowoff[TZD*TYD];
    int bz = blockIdx.z;
    int n = bz >> 4, g = bz & 15;
    int d0 = blockIdx.y * 2;
    int h0 = blockIdx.x * 16;
    int tid = threadIdx.x;                 // 0..127
    int tx = tid & 7, ty = tid >> 3;       // ty 0..15

    const float* inb = (g < 8) ? (x + (size_t)(n*64 + g*GC)*PX)
                               : (g_hfup + (size_t)(n*64 + (g-8)*GC)*PX);
    // stage weights: scalar layout [ch][row(kd*3+kh)][12] (slots 0..8 used)
    if (g < 8) {
        const float* src = g_w1 + (size_t)(n*64 + g*GC)*108;
        for (int idx = tid; idx < GC*108; idx += 128) wsm[idx] = src[idx];
    } else {
        int cbase = (g - 8)*GC;
        for (int idx = tid; idx < GC*81; idx += 128) {
            int ch = idx / 81; int r = idx % 81; int tap = r / 3; int o = r % 3;
            int kd = tap/9, kh = (tap/3)%3, kw = tap%3;
            // hf_up = concat channels 0..63 -> wflow input channels 0..63
            wsm[ch*108 + (kd*3 + kh)*12 + kw*3 + o] =
                wflow[o*(128*27) + (cbase + ch)*27 + tap];
        }
    }
    // row offset LUT
    if (tid < TZD*TYD) {
        int zz = tid / TYD, yy = tid - zz*TYD;
        int gz = d0 - 1 + zz, gy = h0 - 1 + yy;
        bool ok = ((unsigned)gz < 16u) && ((unsigned)gy < 64u);
        rowoff[tid] = ok ? ((gz*64 + gy)*64) : -1;
    }
    // permanent zero halos at idx 3 (gx=-1) and 68 (gx=64), both buffers
    for (int idx = tid; idx < TZD*TYD*2*2; idx += 128) {
        int b2 = idx & 1; int r2 = idx >> 1; int side = r2 & 1; int row = r2 >> 1;
        tile[b2][row*TROW + (side ? 68 : 3)] = 0.f;
    }
    __syncthreads();

    int ch16 = tid & 15;                   // 16B chunk within row (floats 4*ch16..+3)
    int rbase = tid >> 4;                  // 0..7
    unsigned dstb = (unsigned)__cvta_generic_to_shared(&tile[0][0])
                  + (unsigned)((rbase*TROW + 4 + ch16*4) * 4);

#define FILL(BSEL, CPTR) do {                                                  \
    unsigned _db = dstb + (unsigned)((BSEL)*(TSIZE*4));                        \
    _Pragma("unroll")                                                          \
    for (int _k = 0; _k < 9; _k++) {                                           \
        int _ro = rowoff[rbase + 8*_k];                                        \
        int _sz = (_ro < 0) ? 0 : 16;                                          \
        const float* _sp = (CPTR) + ((_ro < 0) ? 0 : _ro) + ch16*4;            \
        asm volatile("cp.async.ca.shared.global [%0], [%1], 16, %2;"           \
            :: "r"(_db + (unsigned)(_k*(8*TROW*4))), "l"(_sp), "r"(_sz));      \
    }                                                                          \
    asm volatile("cp.async.commit_group;" ::: "memory");                       \
} while (0)

// one (kd,kh) weight row against the 5 data pairs, into acc slice DLOC
#define DO_KD(KD, DLOC) do {                                                   \
    const float* wr = wch + ((KD)*3 + kh)*12;                                  \
    F4U W0, W1, W2;                                                            \
    W0.f = *(const float4*)wr;                                                 \
    W1.f = *(const float4*)(wr + 4);                                           \
    W2.f = *(const float4*)(wr + 8);                                           \
    unsigned long long WP[9];                                                  \
    asm("mov.b64 %0, {%1,%1};" : "=l"(WP[0]) : "f"(W0.f.x));                   \
    asm("mov.b64 %0, {%1,%1};" : "=l"(WP[1]) : "f"(W0.f.y));                   \
    asm("mov.b64 %0, {%1,%1};" : "=l"(WP[2]) : "f"(W0.f.z));                   \
    asm("mov.b64 %0, {%1,%1};" : "=l"(WP[3]) : "f"(W0.f.w));                   \
    asm("mov.b64 %0, {%1,%1};" : "=l"(WP[4]) : "f"(W1.f.x));                   \
    asm("mov.b64 %0, {%1,%1};" : "=l"(WP[5]) : "f"(W1.f.y));                   \
    asm("mov.b64 %0, {%1,%1};" : "=l"(WP[6]) : "f"(W1.f.z));                   \
    asm("mov.b64 %0, {%1,%1};" : "=l"(WP[7]) : "f"(W1.f.w));                   \
    asm("mov.b64 %0, {%1,%1};" : "=l"(WP[8]) : "f"(W2.f.x));                   \
    _Pragma("unroll")                                                          \
    for (int o = 0; o < 3; o++) {                                              \
        FMA2(acc[(DLOC)*12 + 0 + o], O0, WP[o]);                               \
        FMA2(acc[(DLOC)*12 + 3 + o], O1, WP[o]);                               \
        FMA2(acc[(DLOC)*12 + 6 + o], O2, WP[o]);                               \
        FMA2(acc[(DLOC)*12 + 9 + o], O3, WP[o]);                               \
        FMA2(acc[(DLOC)*12 + 0 + o], E0, WP[3 + o]);                           \
        FMA2(acc[(DLOC)*12 + 3 + o], E1, WP[3 + o]);                           \
        FMA2(acc[(DLOC)*12 + 6 + o], E2, WP[3 + o]);                           \
        FMA2(acc[(DLOC)*12 + 9 + o], E3, WP[3 + o]);                           \
        FMA2(acc[(DLOC)*12 + 0 + o], O1, WP[6 + o]);                           \
        FMA2(acc[(DLOC)*12 + 3 + o], O2, WP[6 + o]);                           \
        FMA2(acc[(DLOC)*12 + 6 + o], O3, WP[6 + o]);                           \
        FMA2(acc[(DLOC)*12 + 9 + o], O4, WP[6 + o]);                           \
    }                                                                          \
} while (0)

    const float* cptr = inb;
    FILL(0, cptr);

    unsigned long long acc[24];
    #pragma unroll
    for (int j = 0; j < 24; j++) acc[j] = 0ULL;

    for (int c = 0; c < GC; c++) {
        if (c < GC - 1) {
            FILL((c + 1) & 1, cptr + PX);
            asm volatile("cp.async.wait_group 1;" ::: "memory");
        } else {
            asm volatile("cp.async.wait_group 0;" ::: "memory");
        }
        __syncthreads();
        const float* tb = tile[c & 1];
        const float* wch = wsm + c*108;
        #pragma unroll
        for (int zz = 0; zz < 4; zz++) {
            #pragma unroll
            for (int kh = 0; kh < 3; kh++) {
                const float* rowp = tb + (zz*TYD + ty + kh)*TROW + 8*tx;
                F4U A, B, C, D;
                A.f = *(const float4*)rowp;
                B.f = *(const float4*)(rowp + 4);
                C.f = *(const float4*)(rowp + 8);
                D.f = *(const float4*)(rowp + 12);
                unsigned long long O0, O1, O2, O3, O4;
                asm("mov.b64 %0, {%1,%2};" : "=l"(O0) : "f"(A.f.w), "f"(B.f.x));
                asm("mov.b64 %0, {%1,%2};" : "=l"(O1) : "f"(B.f.y), "f"(B.f.z));
                asm("mov.b64 %0, {%1,%2};" : "=l"(O2) : "f"(B.f.w), "f"(C.f.x));
                asm("mov.b64 %0, {%1,%2};" : "=l"(O3) : "f"(C.f.y), "f"(C.f.z));
                asm("mov.b64 %0, {%1,%2};" : "=l"(O4) : "f"(C.f.w), "f"(D.f.x));
                unsigned long long E0 = B.u[0], E1 = B.u[1], E2 = C.u[0], E3 = C.u[1];
                if (zz >= 1) DO_KD(zz - 1, 1);   // input z feeds output d0+1
                if (zz <= 2) DO_KD(zz, 0);       // input z feeds output d0
            }
        }
        __syncthreads();
        cptr += PX;
    }
#undef FILL
#undef DO_KD

    #pragma unroll
    for (int dloc = 0; dloc < 2; dloc++) {
        size_t po = ((size_t)(d0 + dloc)*64 + (h0 + ty))*64 + 8*tx;
        float* fp = g_flowp[g] + (size_t)n*3*PX + po;
        #pragma unroll
        for (int o = 0; o < 3; o++) {
            F2U a0, a1, a2, a3;
            a0.u = acc[dloc*12 + 0 + o]; a1.u = acc[dloc*12 + 3 + o];
            a2.u = acc[dloc*12 + 6 + o]; a3.u = acc[dloc*12 + 9 + o];
            *(float4*)(fp + (size_t)o*PX)     = make_float4(a0.f.x, a0.f.y, a1.f.x, a1.f.y);
            *(float4*)(fp + (size_t)o*PX + 4) = make_float4(a2.f.x, a2.f.y, a3.f.x, a3.f.y);
        }
    }
}

// ------------- K5: sum the 16 partial flows into g_flow --------------------
__global__ void k_fsum() {
    int i = blockIdx.x*256 + threadIdx.x;       // over NB*3*PX/4
    float4 s = make_float4(0.f, 0.f, 0.f, 0.f);
    #pragma unroll
    for (int gg = 0; gg < 16; gg++) {
        float4 v = *(const float4*)&g_flowp[gg][(size_t)i*4];
        s.x += v.x; s.y += v.y; s.z += v.z; s.w += v.w;
    }
    *(float4*)&g_flow[(size_t)i*4] = s;
}

// -------- K6: flow warp + grid sample, channel-interleaved lanes ------------
// 4 threads per voxel; lane cg handles channels {cg*4 + 16j + s}.
__global__ void k_sample(float* __restrict__ out) {
    int tid = threadIdx.x;                    // 256
    int q  = tid >> 2;                        // voxel within block (0..63)
    int cg = tid & 3;                         // channel sub-lane
    int p = blockIdx.x*64 + q;                // 0..65535
    int n = blockIdx.y;
    int w = p & 63, h = (p >> 6) & 63, d = p >> 12;

    size_t fo = (size_t)n*3*PX + p;
    float f0 = g_flow[fo];
    float f1 = g_flow[fo + PX];
    float f2 = g_flow[fo + 2*PX];

    float gx = (w + f0) * (1.f/64.f);
    float gy = (h + f1) * (1.f/64.f);
    float gz = (d + f2) * (1.f/16.f);
    float ix = ((gx + 1.f)*32.f - 1.f)*0.5f;
    float iy = ((gy + 1.f)*32.f - 1.f)*0.5f;
    float iz = ((gz + 1.f)*8.f  - 1.f)*0.5f;
    float fx0 = floorf(ix), fy0 = floorf(iy), fz0 = floorf(iz);
    int x0 = (int)fx0, y0 = (int)fy0, z0 = (int)fz0;
    float fx = ix - fx0, fy = iy - fy0, fz = iz - fz0;
    float wx0 = 1.f - fx, wy0 = 1.f - fy, wz0 = 1.f - fz;

    int x0c = min(max(x0, 0), 31), x1c = min(max(x0 + 1, 0), 31);
    int y0c = min(max(y0, 0), 31), y1c = min(max(y0 + 1, 0), 31);
    int z0c = min(max(z0, 0), 7),  z1c = min(max(z0 + 1, 0), 7);
    bool vx0 = ((unsigned)x0 < 32u), vx1 = ((unsigned)(x0 + 1) < 32u);
    bool vy0 = ((unsigned)y0 < 32u), vy1 = ((unsigned)(y0 + 1) < 32u);
    bool vz0 = ((unsigned)z0 < 8u),  vz1 = ((unsigned)(z0 + 1) < 8u);

    int o[8];
    o[0] = (z0c*32 + y0c)*32 + x0c;
    o[1] = (z0c*32 + y0c)*32 + x1c;
    o[2] = (z0c*32 + y1c)*32 + x0c;
    o[3] = (z0c*32 + y1c)*32 + x1c;
    o[4] = (z1c*32 + y0c)*32 + x0c;
    o[5] = (z1c*32 + y0c)*32 + x1c;
    o[6] = (z1c*32 + y1c)*32 + x0c;
    o[7] = (z1c*32 + y1c)*32 + x1c;
    float t[8];
    t[0] = (vz0 && vy0 && vx0) ? wz0*wy0*wx0 : 0.f;
    t[1] = (vz0 && vy0 && vx1) ? wz0*wy0*fx  : 0.f;
    t[2] = (vz0 && vy1 && vx0) ? wz0*fy*wx0  : 0.f;
    t[3] = (vz0 && vy1 && vx1) ? wz0*fy*fx   : 0.f;
    t[4] = (vz1 && vy0 && vx0) ? fz*wy0*wx0  : 0.f;
    t[5] = (vz1 && vy0 && vx1) ? fz*wy0*fx   : 0.f;
    t[6] = (vz1 && vy1 && vx0) ? fz*fy*wx0   : 0.f;
    t[7] = (vz1 && vy1 && vx1) ? fz*fy*fx    : 0.f;

    // lane cg covers channels cg*4 + 16j + s  (s=0..3), j=0..7
    const float* ytb = g_yT + ((size_t)n*PY)*CYC + cg*4;
    unsigned long long acc[16];
    #pragma unroll
    for (int j = 0; j < 16; j++) acc[j] = 0ULL;
    #pragma unroll
    for (int i = 0; i < 8; i++) {
        const float4* tp = (const float4*)(ytb + (size_t)o[i]*CYC);
        F2U tw; tw.f = make_float2(t[i], t[i]);
        #pragma unroll
        for (int j = 0; j < 8; j++) {
            F4U v; v.f = __ldg(tp + j*4);
            FMA2(acc[2*j],     v.u[0], tw.u);
            FMA2(acc[2*j + 1], v.u[1], tw.u);
        }
    }
    float* ob = out + (size_t)n*CYC*PX + (size_t)(cg*4)*PX + p;
    #pragma unroll
    for (int j = 0; j < 8; j++) {
        F2U a, b2; a.u = acc[2*j]; b2.u = acc[2*j + 1];
        ob[(size_t)(16*j + 0)*PX] = a.f.x;
        ob[(size_t)(16*j + 1)*PX] = a.f.y;
        ob[(size_t)(16*j + 2)*PX] = b2.f.x;
        ob[(size_t)(16*j + 3)*PX] = b2.f.y;
    }
}

// --------------------------------- launch ----------------------------------
extern "C" void kernel_launch(void* const* d_in, const int* in_sizes, int n_in,
                              void* d_out, int out_size) {
    const float* x     = (const float*)d_in[0];
    const float* y     = (const float*)d_in[1];
    const float* wdh   = (const float*)d_in[2];
    const float* wdl   = (const float*)d_in[3];
    const float* wflow = (const float*)d_in[4];
    const float* wa    = (const float*)d_in[5];
    const float* wc    = (const float*)d_in[6];
    float* out = (float*)d_out;

    k_pre<<<2432, 256>>>(y, wdh, x);
    k_prep<<<NB, 256>>>(wdl, wa, wc, wflow);
    k_up<<<(NB*CO*PX/4)/256, 256>>>();
    k_conv3<<<dim3(4, 8, NB*16), 128>>>(x, wflow);
    k_fsum<<<(NB*3*PX/4)/256, 256>>>();
    k_sample<<<dim3(PX/64, NB), 256>>>(out);
}